// round 7
// baseline (speedup 1.0000x reference)
#include <cuda_runtime.h>
#include <math.h>
#include <cstdint>

#define BB 2
#define NH 16
#define TT 2048
#define DD 64
#define EE 1024
#define SRC 128

// Scratch for projected Q/K/V in [B, H, T, D] layout (no cudaMalloc allowed).
__device__ float g_q[BB * NH * TT * DD];
__device__ float g_k[BB * NH * TT * DD];
__device__ float g_v[BB * NH * TT * DD];

__device__ __forceinline__ float to_tf32(float f) {
    float r;
    asm("cvt.rna.tf32.f32 %0, %1;" : "=f"(r) : "f"(f));
    return r;
}

// D += A(16x8) * B(8x8), tf32 inputs (as b32 regs), fp32 accum.
__device__ __forceinline__ void mma_tf32(
    float* d, uint32_t a0, uint32_t a1, uint32_t a2, uint32_t a3,
    uint32_t b0, uint32_t b1)
{
    asm volatile(
        "mma.sync.aligned.m16n8k8.row.col.f32.tf32.tf32.f32 "
        "{%0,%1,%2,%3}, {%4,%5,%6,%7}, {%8,%9}, {%0,%1,%2,%3};"
        : "+f"(d[0]), "+f"(d[1]), "+f"(d[2]), "+f"(d[3])
        : "r"(a0), "r"(a1), "r"(a2), "r"(a3), "r"(b0), "r"(b1));
}

// ===========================================================================
// QKV projection: y = x @ W^T + b, scattered into [B,H,T,D].  tf32 mma.sync.
// Block tile 128x128, 256 threads (8 warps as 4Mx2N; warp tile 32x64).
// K chunks of 32 floats staged in smem (pitch 36 -> conflict-free frags).
// grid = (8, 32, 3)   [unchanged this round]
// ===========================================================================
#define GPITCH 36

__global__ __launch_bounds__(256) void qkv_gemm_tc(
    const float* __restrict__ x,
    const float* __restrict__ Wq, const float* __restrict__ bq,
    const float* __restrict__ Wk, const float* __restrict__ bk,
    const float* __restrict__ Wv, const float* __restrict__ bv)
{
    __shared__ float As[128 * GPITCH];
    __shared__ float Bs[128 * GPITCH];

    const int z = blockIdx.z;
    const float* __restrict__ W    = (z == 0) ? Wq : (z == 1) ? Wk : Wv;
    const float* __restrict__ bias = (z == 0) ? bq : (z == 1) ? bk : bv;
    float* __restrict__ dst        = (z == 0) ? g_q : (z == 1) ? g_k : g_v;

    const int m0 = blockIdx.y * 128;
    const int n0 = blockIdx.x * 128;
    const int tid = threadIdx.x;
    const int lane = tid & 31;
    const int wid = tid >> 5;
    const int wm = wid & 3;        // 0..3 : M warp (32 rows)
    const int wn = wid >> 2;       // 0..1 : N warp (64 cols)
    const int lr = lane >> 2;      // 0..7
    const int lc = lane & 3;       // 0..3

    // cooperative load mapping: 128 rows x 8 float4 cols; 4 f4 per thread
    const int ldrow = tid >> 1;              // 0..127
    const int ldc4a = (tid & 1) * 16;        // 0 or 16 (float index, 4 f4 apart)

    float acc[2][8][4] = {};

    // prefetch chunk 0
    float4 pa[4], pb[4];
    #pragma unroll
    for (int i = 0; i < 4; i++) {
        pa[i] = *(const float4*)&x[(size_t)(m0 + ldrow) * EE + ldc4a + i * 4];
        pb[i] = *(const float4*)&W[(size_t)(n0 + ldrow) * EE + ldc4a + i * 4];
    }

    #pragma unroll 1
    for (int kc = 0; kc < EE / 32; kc++) {
        // store prefetched chunk (tf32-rounded)
        #pragma unroll
        for (int i = 0; i < 4; i++) {
            float4 a = pa[i], b = pb[i];
            a.x = to_tf32(a.x); a.y = to_tf32(a.y); a.z = to_tf32(a.z); a.w = to_tf32(a.w);
            b.x = to_tf32(b.x); b.y = to_tf32(b.y); b.z = to_tf32(b.z); b.w = to_tf32(b.w);
            *(float4*)&As[ldrow * GPITCH + ldc4a + i * 4] = a;
            *(float4*)&Bs[ldrow * GPITCH + ldc4a + i * 4] = b;
        }
        __syncthreads();

        if (kc + 1 < EE / 32) {
            const int k0 = (kc + 1) * 32;
            #pragma unroll
            for (int i = 0; i < 4; i++) {
                pa[i] = *(const float4*)&x[(size_t)(m0 + ldrow) * EE + k0 + ldc4a + i * 4];
                pb[i] = *(const float4*)&W[(size_t)(n0 + ldrow) * EE + k0 + ldc4a + i * 4];
            }
        }

        #pragma unroll
        for (int kk = 0; kk < 32; kk += 8) {
            uint32_t a[2][4];
            #pragma unroll
            for (int mt = 0; mt < 2; mt++) {
                const int r = wm * 32 + mt * 16 + lr;
                a[mt][0] = __float_as_uint(As[r * GPITCH + kk + lc]);
                a[mt][1] = __float_as_uint(As[(r + 8) * GPITCH + kk + lc]);
                a[mt][2] = __float_as_uint(As[r * GPITCH + kk + lc + 4]);
                a[mt][3] = __float_as_uint(As[(r + 8) * GPITCH + kk + lc + 4]);
            }
            #pragma unroll
            for (int j = 0; j < 8; j++) {
                const int nc = wn * 64 + j * 8 + lr;
                uint32_t b0 = __float_as_uint(Bs[nc * GPITCH + kk + lc]);
                uint32_t b1 = __float_as_uint(Bs[nc * GPITCH + kk + lc + 4]);
                mma_tf32(acc[0][j], a[0][0], a[0][1], a[0][2], a[0][3], b0, b1);
                mma_tf32(acc[1][j], a[1][0], a[1][1], a[1][2], a[1][3], b0, b1);
            }
        }
        __syncthreads();
    }

    // Epilogue: add bias, scatter to [B,H,T,D]
    #pragma unroll
    for (int mt = 0; mt < 2; mt++) {
        #pragma unroll
        for (int j = 0; j < 8; j++) {
            const int N = n0 + wn * 64 + j * 8 + 2 * lc;
            const int h = N >> 6, d = N & 63;
            const float b0 = __ldg(&bias[N]), b1 = __ldg(&bias[N + 1]);
            #pragma unroll
            for (int half = 0; half < 2; half++) {
                const int M = m0 + wm * 32 + mt * 16 + lr + half * 8;
                const int bb = M >> 11, t = M & (TT - 1);
                float2 o;
                o.x = acc[mt][j][half * 2 + 0] + b0;
                o.y = acc[mt][j][half * 2 + 1] + b1;
                *(float2*)&dst[(((size_t)(bb * NH + h) * TT) + t) * DD + d] = o;
            }
        }
    }
}

// ===========================================================================
// Flash attention, prefix-causal band (key j valid iff j <= i + SRC).
// One block = (b, h, 128-query tile). 128 threads = 4 warps.
// Each warp owns 32 query rows (2 x m16 tiles) -> every K/V fragment loaded
// from smem feeds TWO mma's, halving per-block LDS traffic vs 8-warp layout.
// Online softmax in registers (quad shuffles), per m-tile.
// Ps overlays the Q staging buffer (Q fragments hoisted to registers first).
// ===========================================================================
#define QP 68          // Qs/Ks/Ps pitch (4 mod 32 -> conflict-free row frags)
#define VP 72          // Vs pitch (8 mod 32 -> conflict-free column frags)
#define SM_QS 0        // 128 x QP floats, reused as Ps after Q-frag hoist
#define SM_KS (128 * QP)
#define SM_VS (128 * QP + 64 * QP)
#define ATTN_SMEM_FLOATS (128 * QP + 64 * QP + 64 * VP)   // 17664 floats = 70656 B

__global__ __launch_bounds__(128, 2) void attn_kernel(float* __restrict__ out)
{
    extern __shared__ float sm[];
    float* Qs = sm + SM_QS;      // staging; becomes Ps inside the loop
    float* Ps = sm + SM_QS;
    float* Ks = sm + SM_KS;
    float* Vs = sm + SM_VS;

    const int qtile = gridDim.x - 1 - blockIdx.x;  // heavy tiles first
    const int h = blockIdx.y;
    const int b = blockIdx.z;
    const int qs = qtile * 128;

    const float* __restrict__ Qb = g_q + (size_t)(b * NH + h) * TT * DD;
    const float* __restrict__ Kb = g_k + (size_t)(b * NH + h) * TT * DD;
    const float* __restrict__ Vb = g_v + (size_t)(b * NH + h) * TT * DD;

    const int tid = threadIdx.x;
    const int lane = tid & 31;
    const int w = tid >> 5;        // warp id 0..3: rows 32w..32w+31
    const int lr = lane >> 2;      // 0..7
    const int lc = lane & 3;       // 0..3

    // Q cooperative load: 2 passes of 64 rows; row = pass*64 + tid/2
    const int qldrow = tid >> 1;            // 0..63
    const int qldc0 = (tid & 1) * 32;       // 0 or 32
    // K/V cooperative load: 64 rows x 64 cols; each thread 32 floats
    const int kldrow = tid >> 1;            // 0..63
    const int kldc0 = (tid & 1) * 32;       // 0 or 32

    // ---- load Q tile (scaled by 1/8, tf32) ----
    #pragma unroll
    for (int rep = 0; rep < 2; rep++) {
        const int row = rep * 64 + qldrow;
        #pragma unroll
        for (int i = 0; i < 8; i++) {
            float4 v = *(const float4*)&Qb[(size_t)(qs + row) * DD + qldc0 + i * 4];
            v.x = to_tf32(v.x * 0.125f); v.y = to_tf32(v.y * 0.125f);
            v.z = to_tf32(v.z * 0.125f); v.w = to_tf32(v.w * 0.125f);
            *(float4*)&Qs[row * QP + qldc0 + i * 4] = v;
        }
    }
    __syncthreads();

    // hoist Q fragments (constant across KV loop): 2 mtiles x 8 ksteps x 4 regs
    uint32_t qa[2][8][4];
    #pragma unroll
    for (int mt = 0; mt < 2; mt++) {
        const int r = w * 32 + mt * 16 + lr;
        #pragma unroll
        for (int ks8 = 0; ks8 < 8; ks8++) {
            const int kk = ks8 * 8;
            qa[mt][ks8][0] = __float_as_uint(Qs[r * QP + kk + lc]);
            qa[mt][ks8][1] = __float_as_uint(Qs[(r + 8) * QP + kk + lc]);
            qa[mt][ks8][2] = __float_as_uint(Qs[r * QP + kk + lc + 4]);
            qa[mt][ks8][3] = __float_as_uint(Qs[(r + 8) * QP + kk + lc + 4]);
        }
    }

    float o[2][8][4] = {};
    float m_lo[2], m_hi[2], l_lo[2], l_hi[2];
    #pragma unroll
    for (int mt = 0; mt < 2; mt++) {
        m_lo[mt] = -1e30f; m_hi[mt] = -1e30f;
        l_lo[mt] = 0.0f;   l_hi[mt] = 0.0f;
    }

    const int ntiles = min(TT / 64, qtile * 2 + 4);

    #pragma unroll 1
    for (int jt = 0; jt < ntiles; jt++) {
        const int kst = jt * 64;
        __syncthreads();   // prev-iter Ks/Vs/Ps reads complete (iter 0: Q hoists done)

        // ---- load K, V tiles (tf32) ----
        #pragma unroll
        for (int i = 0; i < 8; i++) {
            float4 kv = *(const float4*)&Kb[(size_t)(kst + kldrow) * DD + kldc0 + i * 4];
            kv.x = to_tf32(kv.x); kv.y = to_tf32(kv.y);
            kv.z = to_tf32(kv.z); kv.w = to_tf32(kv.w);
            *(float4*)&Ks[kldrow * QP + kldc0 + i * 4] = kv;
            float4 vv = *(const float4*)&Vb[(size_t)(kst + kldrow) * DD + kldc0 + i * 4];
            vv.x = to_tf32(vv.x); vv.y = to_tf32(vv.y);
            vv.z = to_tf32(vv.z); vv.w = to_tf32(vv.w);
            *(float4*)&Vs[kldrow * VP + kldc0 + i * 4] = vv;
        }
        __syncthreads();

        // ---- S = Q @ K^T : each K fragment feeds both m-tiles ----
        float s[2][8][4] = {};
        #pragma unroll
        for (int ks8 = 0; ks8 < 8; ks8++) {
            const int kk = ks8 * 8;
            #pragma unroll
            for (int j = 0; j < 8; j++) {
                const int key = j * 8 + lr;
                uint32_t b0 = __float_as_uint(Ks[key * QP + kk + lc]);
                uint32_t b1 = __float_as_uint(Ks[key * QP + kk + lc + 4]);
                mma_tf32(s[0][j], qa[0][ks8][0], qa[0][ks8][1], qa[0][ks8][2], qa[0][ks8][3], b0, b1);
                mma_tf32(s[1][j], qa[1][ks8][0], qa[1][ks8][1], qa[1][ks8][2], qa[1][ks8][3], b0, b1);
            }
        }

        // ---- mask (partially-banded tiles only) ----
        if ((kst + 63) > (qs + SRC)) {
            #pragma unroll
            for (int mt = 0; mt < 2; mt++) {
                const int rlo = qs + w * 32 + mt * 16 + lr;
                #pragma unroll
                for (int j = 0; j < 8; j++) {
                    const int c0 = kst + j * 8 + 2 * lc;
                    if (c0     > rlo + SRC)     s[mt][j][0] = -1e30f;
                    if (c0 + 1 > rlo + SRC)     s[mt][j][1] = -1e30f;
                    if (c0     > rlo + 8 + SRC) s[mt][j][2] = -1e30f;
                    if (c0 + 1 > rlo + 8 + SRC) s[mt][j][3] = -1e30f;
                }
            }
        }

        // ---- online softmax per m-tile (quad shuffles) ----
        #pragma unroll
        for (int mt = 0; mt < 2; mt++) {
            float mx_lo = -1e30f, mx_hi = -1e30f;
            #pragma unroll
            for (int j = 0; j < 8; j++) {
                mx_lo = fmaxf(mx_lo, fmaxf(s[mt][j][0], s[mt][j][1]));
                mx_hi = fmaxf(mx_hi, fmaxf(s[mt][j][2], s[mt][j][3]));
            }
            #pragma unroll
            for (int off = 1; off <= 2; off <<= 1) {
                mx_lo = fmaxf(mx_lo, __shfl_xor_sync(0xffffffffu, mx_lo, off));
                mx_hi = fmaxf(mx_hi, __shfl_xor_sync(0xffffffffu, mx_hi, off));
            }
            const float mn_lo = fmaxf(m_lo[mt], mx_lo);
            const float mn_hi = fmaxf(m_hi[mt], mx_hi);
            const float al_lo = __expf(m_lo[mt] - mn_lo);
            const float al_hi = __expf(m_hi[mt] - mn_hi);
            m_lo[mt] = mn_lo; m_hi[mt] = mn_hi;

            float sum_lo = 0.0f, sum_hi = 0.0f;
            const int prow = w * 32 + mt * 16 + lr;
            #pragma unroll
            for (int j = 0; j < 8; j++) {
                float p0 = __expf(s[mt][j][0] - mn_lo);
                float p1 = __expf(s[mt][j][1] - mn_lo);
                float p2 = __expf(s[mt][j][2] - mn_hi);
                float p3 = __expf(s[mt][j][3] - mn_hi);
                sum_lo += p0 + p1;
                sum_hi += p2 + p3;
                float2 vlo = make_float2(to_tf32(p0), to_tf32(p1));
                float2 vhi = make_float2(to_tf32(p2), to_tf32(p3));
                *(float2*)&Ps[prow * QP + j * 8 + 2 * lc] = vlo;
                *(float2*)&Ps[(prow + 8) * QP + j * 8 + 2 * lc] = vhi;
                o[mt][j][0] *= al_lo; o[mt][j][1] *= al_lo;
                o[mt][j][2] *= al_hi; o[mt][j][3] *= al_hi;
            }
            #pragma unroll
            for (int off = 1; off <= 2; off <<= 1) {
                sum_lo += __shfl_xor_sync(0xffffffffu, sum_lo, off);
                sum_hi += __shfl_xor_sync(0xffffffffu, sum_hi, off);
            }
            l_lo[mt] = l_lo[mt] * al_lo + sum_lo;
            l_hi[mt] = l_hi[mt] * al_hi + sum_hi;
        }
        __syncwarp();   // Ps rows are warp-private; make stores visible in-warp

        // ---- O += P @ V : each V fragment feeds both m-tiles ----
        #pragma unroll
        for (int ks8 = 0; ks8 < 8; ks8++) {
            const int k0 = ks8 * 8;
            uint32_t a[2][4];
            #pragma unroll
            for (int mt = 0; mt < 2; mt++) {
                const int prow = w * 32 + mt * 16 + lr;
                a[mt][0] = __float_as_uint(Ps[prow * QP + k0 + lc]);
                a[mt][1] = __float_as_uint(Ps[(prow + 8) * QP + k0 + lc]);
                a[mt][2] = __float_as_uint(Ps[prow * QP + k0 + lc + 4]);
                a[mt][3] = __float_as_uint(Ps[(prow + 8) * QP + k0 + lc + 4]);
            }
            #pragma unroll
            for (int j = 0; j < 8; j++) {
                uint32_t b0 = __float_as_uint(Vs[(k0 + lc) * VP + j * 8 + lr]);
                uint32_t b1 = __float_as_uint(Vs[(k0 + lc + 4) * VP + j * 8 + lr]);
                mma_tf32(o[0][j], a[0][0], a[0][1], a[0][2], a[0][3], b0, b1);
                mma_tf32(o[1][j], a[1][0], a[1][1], a[1][2], a[1][3], b0, b1);
            }
        }
    }

    // ---- finalize: scale by 1/l, write out ----
    #pragma unroll
    for (int mt = 0; mt < 2; mt++) {
        const float li_lo = 1.0f / l_lo[mt];
        const float li_hi = 1.0f / l_hi[mt];
        const int t_lo = qs + w * 32 + mt * 16 + lr;
        #pragma unroll
        for (int j = 0; j < 8; j++) {
            const int d = j * 8 + 2 * lc;
            float2 v0 = make_float2(o[mt][j][0] * li_lo, o[mt][j][1] * li_lo);
            float2 v1 = make_float2(o[mt][j][2] * li_hi, o[mt][j][3] * li_hi);
            *(float2*)&out[((size_t)(b * TT + t_lo)) * EE + h * DD + d] = v0;
            *(float2*)&out[((size_t)(b * TT + t_lo + 8)) * EE + h * DD + d] = v1;
        }
    }
}

// ---------------------------------------------------------------------------
extern "C" void kernel_launch(void* const* d_in, const int* in_sizes, int n_in,
                              void* d_out, int out_size)
{
    (void)in_sizes; (void)n_in; (void)out_size;
    const float* x  = (const float*)d_in[0];
    const float* Wq = (const float*)d_in[1];
    const float* bq = (const float*)d_in[2];
    const float* Wk = (const float*)d_in[3];
    const float* bk = (const float*)d_in[4];
    const float* Wv = (const float*)d_in[5];
    const float* bv = (const float*)d_in[6];
    float* out = (float*)d_out;

    cudaFuncSetAttribute(attn_kernel,
                         cudaFuncAttributeMaxDynamicSharedMemorySize,
                         (int)(ATTN_SMEM_FLOATS * sizeof(float)));

    dim3 ggrid(EE / 128, (BB * TT) / 128, 3);   // (8, 32, 3)
    qkv_gemm_tc<<<ggrid, 256>>>(x, Wq, bq, Wk, bk, Wv, bv);

    dim3 agrid(TT / 128, NH, BB);               // (16, 16, 2)
    attn_kernel<<<agrid, 128, ATTN_SMEM_FLOATS * sizeof(float)>>>(out);
}

// round 8
// speedup vs baseline: 1.6642x; 1.6642x over previous
#include <cuda_runtime.h>
#include <math.h>
#include <cstdint>

#define BB 2
#define NH 16
#define TT 2048
#define DD 64
#define EE 1024
#define SRC 128

// Scratch for projected Q/K/V in [B, H, T, D] layout (no cudaMalloc allowed).
// Values stored tf32-rounded (Q additionally pre-scaled by 1/8) — MMA-ready.
__device__ float g_q[BB * NH * TT * DD];
__device__ float g_k[BB * NH * TT * DD];
__device__ float g_v[BB * NH * TT * DD];

__device__ __forceinline__ float to_tf32(float f) {
    float r;
    asm("cvt.rna.tf32.f32 %0, %1;" : "=f"(r) : "f"(f));
    return r;
}

// D += A(16x8) * B(8x8), tf32 inputs (as b32 regs), fp32 accum.
__device__ __forceinline__ void mma_tf32(
    float* d, uint32_t a0, uint32_t a1, uint32_t a2, uint32_t a3,
    uint32_t b0, uint32_t b1)
{
    asm volatile(
        "mma.sync.aligned.m16n8k8.row.col.f32.tf32.tf32.f32 "
        "{%0,%1,%2,%3}, {%4,%5,%6,%7}, {%8,%9}, {%0,%1,%2,%3};"
        : "+f"(d[0]), "+f"(d[1]), "+f"(d[2]), "+f"(d[3])
        : "r"(a0), "r"(a1), "r"(a2), "r"(a3), "r"(b0), "r"(b1));
}

__device__ __forceinline__ void cp_async16(uint32_t smem_addr, const void* gptr) {
    asm volatile("cp.async.cg.shared.global [%0], [%1], 16;"
                 :: "r"(smem_addr), "l"(gptr));
}
#define CP_COMMIT() asm volatile("cp.async.commit_group;" ::: "memory")
#define CP_WAIT(N)  asm volatile("cp.async.wait_group %0;" :: "n"(N) : "memory")

// ===========================================================================
// QKV projection: y = x @ W^T + b, scattered into [B,H,T,D].  tf32 mma.sync.
// Block tile 128x128, 256 threads (8 warps as 4Mx2N; warp tile 32x64).
// Epilogue rounds outputs to tf32 (Q also scaled by 1/8) so the attention
// kernel can copy them into smem without any per-element math.
// grid = (8, 32, 3)
// ===========================================================================
#define GPITCH 36

__global__ __launch_bounds__(256) void qkv_gemm_tc(
    const float* __restrict__ x,
    const float* __restrict__ Wq, const float* __restrict__ bq,
    const float* __restrict__ Wk, const float* __restrict__ bk,
    const float* __restrict__ Wv, const float* __restrict__ bv)
{
    __shared__ float As[128 * GPITCH];
    __shared__ float Bs[128 * GPITCH];

    const int z = blockIdx.z;
    const float* __restrict__ W    = (z == 0) ? Wq : (z == 1) ? Wk : Wv;
    const float* __restrict__ bias = (z == 0) ? bq : (z == 1) ? bk : bv;
    float* __restrict__ dst        = (z == 0) ? g_q : (z == 1) ? g_k : g_v;
    const float osc = (z == 0) ? 0.125f : 1.0f;

    const int m0 = blockIdx.y * 128;
    const int n0 = blockIdx.x * 128;
    const int tid = threadIdx.x;
    const int lane = tid & 31;
    const int wid = tid >> 5;
    const int wm = wid & 3;        // 0..3 : M warp (32 rows)
    const int wn = wid >> 2;       // 0..1 : N warp (64 cols)
    const int lr = lane >> 2;      // 0..7
    const int lc = lane & 3;       // 0..3

    // cooperative load mapping: 128 rows x 8 float4 cols; 4 f4 per thread
    const int ldrow = tid >> 1;              // 0..127
    const int ldc4a = (tid & 1) * 16;        // 0 or 16 (float index, 4 f4 apart)

    float acc[2][8][4] = {};

    // prefetch chunk 0
    float4 pa[4], pb[4];
    #pragma unroll
    for (int i = 0; i < 4; i++) {
        pa[i] = *(const float4*)&x[(size_t)(m0 + ldrow) * EE + ldc4a + i * 4];
        pb[i] = *(const float4*)&W[(size_t)(n0 + ldrow) * EE + ldc4a + i * 4];
    }

    #pragma unroll 1
    for (int kc = 0; kc < EE / 32; kc++) {
        // store prefetched chunk (tf32-rounded)
        #pragma unroll
        for (int i = 0; i < 4; i++) {
            float4 a = pa[i], b = pb[i];
            a.x = to_tf32(a.x); a.y = to_tf32(a.y); a.z = to_tf32(a.z); a.w = to_tf32(a.w);
            b.x = to_tf32(b.x); b.y = to_tf32(b.y); b.z = to_tf32(b.z); b.w = to_tf32(b.w);
            *(float4*)&As[ldrow * GPITCH + ldc4a + i * 4] = a;
            *(float4*)&Bs[ldrow * GPITCH + ldc4a + i * 4] = b;
        }
        __syncthreads();

        if (kc + 1 < EE / 32) {
            const int k0 = (kc + 1) * 32;
            #pragma unroll
            for (int i = 0; i < 4; i++) {
                pa[i] = *(const float4*)&x[(size_t)(m0 + ldrow) * EE + k0 + ldc4a + i * 4];
                pb[i] = *(const float4*)&W[(size_t)(n0 + ldrow) * EE + k0 + ldc4a + i * 4];
            }
        }

        #pragma unroll
        for (int kk = 0; kk < 32; kk += 8) {
            uint32_t a[2][4];
            #pragma unroll
            for (int mt = 0; mt < 2; mt++) {
                const int r = wm * 32 + mt * 16 + lr;
                a[mt][0] = __float_as_uint(As[r * GPITCH + kk + lc]);
                a[mt][1] = __float_as_uint(As[(r + 8) * GPITCH + kk + lc]);
                a[mt][2] = __float_as_uint(As[r * GPITCH + kk + lc + 4]);
                a[mt][3] = __float_as_uint(As[(r + 8) * GPITCH + kk + lc + 4]);
            }
            #pragma unroll
            for (int j = 0; j < 8; j++) {
                const int nc = wn * 64 + j * 8 + lr;
                uint32_t b0 = __float_as_uint(Bs[nc * GPITCH + kk + lc]);
                uint32_t b1 = __float_as_uint(Bs[nc * GPITCH + kk + lc + 4]);
                mma_tf32(acc[0][j], a[0][0], a[0][1], a[0][2], a[0][3], b0, b1);
                mma_tf32(acc[1][j], a[1][0], a[1][1], a[1][2], a[1][3], b0, b1);
            }
        }
        __syncthreads();
    }

    // Epilogue: add bias, scale (Q only), round to tf32, scatter to [B,H,T,D]
    #pragma unroll
    for (int mt = 0; mt < 2; mt++) {
        #pragma unroll
        for (int j = 0; j < 8; j++) {
            const int N = n0 + wn * 64 + j * 8 + 2 * lc;
            const int h = N >> 6, d = N & 63;
            const float b0 = __ldg(&bias[N]), b1 = __ldg(&bias[N + 1]);
            #pragma unroll
            for (int half = 0; half < 2; half++) {
                const int M = m0 + wm * 32 + mt * 16 + lr + half * 8;
                const int bb = M >> 11, t = M & (TT - 1);
                float2 o;
                o.x = to_tf32((acc[mt][j][half * 2 + 0] + b0) * osc);
                o.y = to_tf32((acc[mt][j][half * 2 + 1] + b1) * osc);
                *(float2*)&dst[(((size_t)(bb * NH + h) * TT) + t) * DD + d] = o;
            }
        }
    }
}

// ===========================================================================
// Flash attention, prefix-causal band (key j valid iff j <= i + SRC).
// One block = (b, h, 128-query tile). 256 threads (8 warps); warp = 16 rows.
// K/V tiles double-buffered via cp.async (inputs are pre-rounded tf32, so
// loads are pure 16B copies). Online softmax in registers (quad shuffles).
// Ps overlays the Q staging buffer (Q fragments hoisted to registers first).
// ===========================================================================
#define QP 68          // Qs/Ks/Ps pitch (4 mod 32 -> conflict-free row frags)
#define VP 72          // Vs pitch (8 mod 32 -> conflict-free column frags)
#define SM_QS 0        // 128 x QP floats, reused as Ps after Q-frag hoist
#define SM_K0 (128 * QP)              // 8704
#define SM_K1 (SM_K0 + 64 * QP)       // 13056
#define SM_V0 (SM_K1 + 64 * QP)       // 17408
#define SM_V1 (SM_V0 + 64 * VP)       // 22016
#define ATTN_SMEM_FLOATS (SM_V1 + 64 * VP)   // 26624 floats = 106496 B

__global__ __launch_bounds__(256) void attn_kernel(float* __restrict__ out)
{
    extern __shared__ float sm[];
    float* Ps = sm + SM_QS;

    const int qtile = gridDim.x - 1 - blockIdx.x;  // heavy tiles first
    const int h = blockIdx.y;
    const int b = blockIdx.z;
    const int qs = qtile * 128;

    const float* __restrict__ Qb = g_q + (size_t)(b * NH + h) * TT * DD;
    const float* __restrict__ Kb = g_k + (size_t)(b * NH + h) * TT * DD;
    const float* __restrict__ Vb = g_v + (size_t)(b * NH + h) * TT * DD;

    const int tid = threadIdx.x;
    const int lane = tid & 31;
    const int w = tid >> 5;        // warp id 0..7: rows 16w..16w+15
    const int lr = lane >> 2;      // 0..7
    const int lc = lane & 3;       // 0..3

    const uint32_t smb = (uint32_t)__cvta_generic_to_shared(sm);

    // Q cooperative copy: 128 rows x 64 cols; 8 x 16B per thread
    const int qldrow = tid >> 1;            // 0..127
    const int qldc0 = (tid & 1) * 32;       // 0 or 32
    // K/V cooperative copy: 64 rows x 64 cols; 4 x 16B per thread each
    const int kldrow = tid >> 2;            // 0..63
    const int kldc0 = (tid & 3) * 16;       // 0,16,32,48

    // ---- prologue: async-copy Q tile (group), then K/V tile 0 (group) ----
    #pragma unroll
    for (int i = 0; i < 8; i++)
        cp_async16(smb + (uint32_t)(SM_QS + qldrow * QP + qldc0 + i * 4) * 4,
                   &Qb[(size_t)(qs + qldrow) * DD + qldc0 + i * 4]);
    CP_COMMIT();
    #pragma unroll
    for (int i = 0; i < 4; i++) {
        cp_async16(smb + (uint32_t)(SM_K0 + kldrow * QP + kldc0 + i * 4) * 4,
                   &Kb[(size_t)kldrow * DD + kldc0 + i * 4]);
        cp_async16(smb + (uint32_t)(SM_V0 + kldrow * VP + kldc0 + i * 4) * 4,
                   &Vb[(size_t)kldrow * DD + kldc0 + i * 4]);
    }
    CP_COMMIT();

    CP_WAIT(1);          // Q complete (tile0 may still be in flight)
    __syncthreads();

    // hoist Q fragments (constant across KV loop): 8 ksteps x 4 regs
    uint32_t qa[8][4];
    {
        const float* Qs = sm + SM_QS;
        const int r = w * 16 + lr;
        #pragma unroll
        for (int ks8 = 0; ks8 < 8; ks8++) {
            const int kk = ks8 * 8;
            qa[ks8][0] = __float_as_uint(Qs[r * QP + kk + lc]);
            qa[ks8][1] = __float_as_uint(Qs[(r + 8) * QP + kk + lc]);
            qa[ks8][2] = __float_as_uint(Qs[r * QP + kk + lc + 4]);
            qa[ks8][3] = __float_as_uint(Qs[(r + 8) * QP + kk + lc + 4]);
        }
    }

    float o[8][4] = {};
    float m_lo = -1e30f, m_hi = -1e30f, l_lo = 0.0f, l_hi = 0.0f;

    const int ntiles = min(TT / 64, qtile * 2 + 4);

    #pragma unroll 1
    for (int jt = 0; jt < ntiles; jt++) {
        const int kst = jt * 64;
        __syncthreads();   // all warps done with iter jt-1 (incl. buf (jt+1)&1 reads)

        // ---- issue async copies for tile jt+1 into the other buffer ----
        if (jt + 1 < ntiles) {
            const int nk = (jt + 1) * 64;
            const uint32_t koff = ((jt + 1) & 1) ? SM_K1 : SM_K0;
            const uint32_t voff = ((jt + 1) & 1) ? SM_V1 : SM_V0;
            #pragma unroll
            for (int i = 0; i < 4; i++) {
                cp_async16(smb + (koff + kldrow * QP + kldc0 + i * 4) * 4,
                           &Kb[(size_t)(nk + kldrow) * DD + kldc0 + i * 4]);
                cp_async16(smb + (voff + kldrow * VP + kldc0 + i * 4) * 4,
                           &Vb[(size_t)(nk + kldrow) * DD + kldc0 + i * 4]);
            }
            CP_COMMIT();
            CP_WAIT(1);    // tile jt complete; jt+1 may fly
        } else {
            CP_WAIT(0);    // drain: tile jt complete
        }
        __syncthreads();

        const float* Ks = sm + ((jt & 1) ? SM_K1 : SM_K0);
        const float* Vs = sm + ((jt & 1) ? SM_V1 : SM_V0);

        // ---- S = Q @ K^T ----
        float s[8][4] = {};
        #pragma unroll
        for (int ks8 = 0; ks8 < 8; ks8++) {
            const int kk = ks8 * 8;
            #pragma unroll
            for (int j = 0; j < 8; j++) {
                const int key = j * 8 + lr;
                uint32_t b0 = __float_as_uint(Ks[key * QP + kk + lc]);
                uint32_t b1 = __float_as_uint(Ks[key * QP + kk + lc + 4]);
                mma_tf32(s[j], qa[ks8][0], qa[ks8][1], qa[ks8][2], qa[ks8][3], b0, b1);
            }
        }

        // ---- mask (partially-banded tiles only) ----
        if ((kst + 63) > (qs + SRC)) {
            const int rlo = qs + w * 16 + lr;
            #pragma unroll
            for (int j = 0; j < 8; j++) {
                const int c0 = kst + j * 8 + 2 * lc;
                if (c0     > rlo + SRC)     s[j][0] = -1e30f;
                if (c0 + 1 > rlo + SRC)     s[j][1] = -1e30f;
                if (c0     > rlo + 8 + SRC) s[j][2] = -1e30f;
                if (c0 + 1 > rlo + 8 + SRC) s[j][3] = -1e30f;
            }
        }

        // ---- online softmax (rows r=lane>>2 and r+8; quad shuffles) ----
        float mx_lo = -1e30f, mx_hi = -1e30f;
        #pragma unroll
        for (int j = 0; j < 8; j++) {
            mx_lo = fmaxf(mx_lo, fmaxf(s[j][0], s[j][1]));
            mx_hi = fmaxf(mx_hi, fmaxf(s[j][2], s[j][3]));
        }
        #pragma unroll
        for (int off = 1; off <= 2; off <<= 1) {
            mx_lo = fmaxf(mx_lo, __shfl_xor_sync(0xffffffffu, mx_lo, off));
            mx_hi = fmaxf(mx_hi, __shfl_xor_sync(0xffffffffu, mx_hi, off));
        }
        const float mn_lo = fmaxf(m_lo, mx_lo);
        const float mn_hi = fmaxf(m_hi, mx_hi);
        const float al_lo = __expf(m_lo - mn_lo);
        const float al_hi = __expf(m_hi - mn_hi);
        m_lo = mn_lo; m_hi = mn_hi;

        float sum_lo = 0.0f, sum_hi = 0.0f;
        const int prow = w * 16 + lr;
        #pragma unroll
        for (int j = 0; j < 8; j++) {
            float p0 = __expf(s[j][0] - mn_lo);
            float p1 = __expf(s[j][1] - mn_lo);
            float p2 = __expf(s[j][2] - mn_hi);
            float p3 = __expf(s[j][3] - mn_hi);
            sum_lo += p0 + p1;
            sum_hi += p2 + p3;
            float2 vlo = make_float2(to_tf32(p0), to_tf32(p1));
            float2 vhi = make_float2(to_tf32(p2), to_tf32(p3));
            *(float2*)&Ps[prow * QP + j * 8 + 2 * lc] = vlo;
            *(float2*)&Ps[(prow + 8) * QP + j * 8 + 2 * lc] = vhi;
            o[j][0] *= al_lo; o[j][1] *= al_lo;
            o[j][2] *= al_hi; o[j][3] *= al_hi;
        }
        #pragma unroll
        for (int off = 1; off <= 2; off <<= 1) {
            sum_lo += __shfl_xor_sync(0xffffffffu, sum_lo, off);
            sum_hi += __shfl_xor_sync(0xffffffffu, sum_hi, off);
        }
        l_lo = l_lo * al_lo + sum_lo;
        l_hi = l_hi * al_hi + sum_hi;
        __syncwarp();   // Ps rows are warp-private; make stores visible in-warp

        // ---- O += P @ V ----
        #pragma unroll
        for (int ks8 = 0; ks8 < 8; ks8++) {
            const int k0 = ks8 * 8;
            uint32_t a0 = __float_as_uint(Ps[prow * QP + k0 + lc]);
            uint32_t a1 = __float_as_uint(Ps[(prow + 8) * QP + k0 + lc]);
            uint32_t a2 = __float_as_uint(Ps[prow * QP + k0 + lc + 4]);
            uint32_t a3 = __float_as_uint(Ps[(prow + 8) * QP + k0 + lc + 4]);
            #pragma unroll
            for (int j = 0; j < 8; j++) {
                uint32_t b0 = __float_as_uint(Vs[(k0 + lc) * VP + j * 8 + lr]);
                uint32_t b1 = __float_as_uint(Vs[(k0 + lc + 4) * VP + j * 8 + lr]);
                mma_tf32(o[j], a0, a1, a2, a3, b0, b1);
            }
        }
    }

    // ---- finalize: scale by 1/l, write out ----
    const float li_lo = 1.0f / l_lo;
    const float li_hi = 1.0f / l_hi;
    const int t_lo = qs + w * 16 + lr;
    #pragma unroll
    for (int j = 0; j < 8; j++) {
        const int d = j * 8 + 2 * lc;
        float2 v0 = make_float2(o[j][0] * li_lo, o[j][1] * li_lo);
        float2 v1 = make_float2(o[j][2] * li_hi, o[j][3] * li_hi);
        *(float2*)&out[((size_t)(b * TT + t_lo)) * EE + h * DD + d] = v0;
        *(float2*)&out[((size_t)(b * TT + t_lo + 8)) * EE + h * DD + d] = v1;
    }
}

// ---------------------------------------------------------------------------
extern "C" void kernel_launch(void* const* d_in, const int* in_sizes, int n_in,
                              void* d_out, int out_size)
{
    (void)in_sizes; (void)n_in; (void)out_size;
    const float* x  = (const float*)d_in[0];
    const float* Wq = (const float*)d_in[1];
    const float* bq = (const float*)d_in[2];
    const float* Wk = (const float*)d_in[3];
    const float* bk = (const float*)d_in[4];
    const float* Wv = (const float*)d_in[5];
    const float* bv = (const float*)d_in[6];
    float* out = (float*)d_out;

    cudaFuncSetAttribute(attn_kernel,
                         cudaFuncAttributeMaxDynamicSharedMemorySize,
                         (int)(ATTN_SMEM_FLOATS * sizeof(float)));

    dim3 ggrid(EE / 128, (BB * TT) / 128, 3);   // (8, 32, 3)
    qkv_gemm_tc<<<ggrid, 256>>>(x, Wq, bq, Wk, bk, Wv, bv);

    dim3 agrid(TT / 128, NH, BB);               // (16, 16, 2)
    attn_kernel<<<agrid, 256, ATTN_SMEM_FLOATS * sizeof(float)>>>(out);
}

// round 9
// speedup vs baseline: 1.8303x; 1.0998x over previous
#include <cuda_runtime.h>
#include <math.h>
#include <cstdint>

#define BB 2
#define NH 16
#define TT 2048
#define DD 64
#define EE 1024
#define SRC 128

// Scratch (no cudaMalloc allowed).
// g_q/g_k/g_v: projected tensors, tf32-rounded (Q pre-scaled by 1/8), [B,H,T,D].
// g_xt / g_wt: tf32-rounded, 32-chunk fragment-permuted copies of x and W.
__device__ float g_q[BB * NH * TT * DD];
__device__ float g_k[BB * NH * TT * DD];
__device__ float g_v[BB * NH * TT * DD];
__device__ float g_xt[BB * TT * EE];
__device__ float g_wt[3][EE * EE];

__device__ __forceinline__ float to_tf32(float f) {
    float r;
    asm("cvt.rna.tf32.f32 %0, %1;" : "=f"(r) : "f"(f));
    return r;
}

// D += A(16x8) * B(8x8), tf32 inputs (as b32 regs), fp32 accum.
__device__ __forceinline__ void mma_tf32(
    float* d, uint32_t a0, uint32_t a1, uint32_t a2, uint32_t a3,
    uint32_t b0, uint32_t b1)
{
    asm volatile(
        "mma.sync.aligned.m16n8k8.row.col.f32.tf32.tf32.f32 "
        "{%0,%1,%2,%3}, {%4,%5,%6,%7}, {%8,%9}, {%0,%1,%2,%3};"
        : "+f"(d[0]), "+f"(d[1]), "+f"(d[2]), "+f"(d[3])
        : "r"(a0), "r"(a1), "r"(a2), "r"(a3), "r"(b0), "r"(b1));
}

__device__ __forceinline__ void cp_async16(uint32_t smem_addr, const void* gptr) {
    asm volatile("cp.async.cg.shared.global [%0], [%1], 16;"
                 :: "r"(smem_addr), "l"(gptr));
}
#define CP_COMMIT() asm volatile("cp.async.commit_group;" ::: "memory")
#define CP_WAIT(N)  asm volatile("cp.async.wait_group %0;" :: "n"(N) : "memory")

// ===========================================================================
// Convert kernel: tf32-round x and Wq/Wk/Wv into g_xt / g_wt with each
// 32-column chunk permuted fragment-major: c'(k) = (k%4)*8 + k/4.
// One float4 (k0..k0+3, k0%4==0) scatters to base + {0,8,16,24}.
// ===========================================================================
#define NX4 ((BB * TT * EE) / 4)   // 1048576
#define NW4 ((EE * EE) / 4)        // 262144

__global__ __launch_bounds__(256) void convert_kernel(
    const float* __restrict__ x,
    const float* __restrict__ Wq,
    const float* __restrict__ Wk,
    const float* __restrict__ Wv)
{
    const int idx = blockIdx.x * blockDim.x + threadIdx.x;
    const float* __restrict__ src;
    float* __restrict__ dst;
    int li;
    if (idx < NX4) {
        src = x; dst = g_xt; li = idx;
    } else {
        const int t = idx - NX4;
        const int z = t / NW4;
        li = t - z * NW4;
        src = (z == 0) ? Wq : (z == 1) ? Wk : Wv;
        dst = g_wt[z];
    }
    const float4 v = ((const float4*)src)[li];
    const int f = li * 4;
    const int row = f >> 10;
    const int col = f & 1023;
    const int ch = col >> 5, kc = col & 31;          // kc % 4 == 0
    const int base = (row << 10) | (ch << 5) | (kc >> 2);
    dst[base + 0]  = to_tf32(v.x);
    dst[base + 8]  = to_tf32(v.y);
    dst[base + 16] = to_tf32(v.z);
    dst[base + 24] = to_tf32(v.w);
}

// ===========================================================================
// QKV projection: y = x @ W^T + b, scattered into [B,H,T,D].  tf32 mma.sync.
// Operands come pre-rounded + fragment-permuted from g_xt/g_wt, so the whole
// load path is cp.async (double-buffered, 1 barrier per 32-K chunk) and
// fragment reads are conflict-free LDS.128.
// Block tile 128x128, 256 threads (8 warps as 4Mx2N; warp tile 32x64).
// Epilogue rounds outputs to tf32 (Q also scaled by 1/8).
// grid = (8, 32, 3)
// ===========================================================================
#define GP 36                 // smem row pitch (floats); 144B, 16B-aligned
#define GBUF (128 * GP)       // 4608 floats per tile buffer
#define G_A0 0
#define G_A1 GBUF
#define G_B0 (2 * GBUF)
#define G_B1 (3 * GBUF)
#define GEMM_SMEM_FLOATS (4 * GBUF)   // 18432 floats = 73728 B

__global__ __launch_bounds__(256, 2) void qkv_gemm_tc(
    const float* __restrict__ bq,
    const float* __restrict__ bk,
    const float* __restrict__ bv)
{
    extern __shared__ float smem[];

    const int z = blockIdx.z;
    const float* __restrict__ Wt   = g_wt[z];
    const float* __restrict__ bias = (z == 0) ? bq : (z == 1) ? bk : bv;
    float* __restrict__ dst        = (z == 0) ? g_q : (z == 1) ? g_k : g_v;
    const float osc = (z == 0) ? 0.125f : 1.0f;

    const int m0 = blockIdx.y * 128;
    const int n0 = blockIdx.x * 128;
    const int tid = threadIdx.x;
    const int lane = tid & 31;
    const int wid = tid >> 5;
    const int wm = wid & 3;        // 0..3 : M warp (32 rows)
    const int wn = wid >> 2;       // 0..1 : N warp (64 cols)
    const int lr = lane >> 2;      // 0..7
    const int lc = lane & 3;       // 0..3

    const uint32_t smb = (uint32_t)__cvta_generic_to_shared(smem);

    // cooperative cp.async mapping: 128 rows x 8 f4; 4 f4 per thread per tile
    // id = tid + i*256 -> row = id>>3 (0..127), c4 = (id&7)*4
    // prologue: chunk 0 -> buffer 0
    #pragma unroll
    for (int i = 0; i < 4; i++) {
        const int id = tid + i * 256;
        const int row = id >> 3;
        const int c4 = (id & 7) * 4;
        cp_async16(smb + (uint32_t)(G_A0 + row * GP + c4) * 4,
                   &g_xt[(size_t)(m0 + row) * EE + c4]);
        cp_async16(smb + (uint32_t)(G_B0 + row * GP + c4) * 4,
                   &Wt[(size_t)(n0 + row) * EE + c4]);
    }
    CP_COMMIT();

    float acc[2][8][4] = {};

    #pragma unroll 1
    for (int c = 0; c < EE / 32; c++) {
        CP_WAIT(0);          // chunk c landed (only group outstanding)
        __syncthreads();     // visible to all; compute(c-1) done -> buf^1 free

        if (c + 1 < EE / 32) {
            const int k0 = (c + 1) * 32;
            const uint32_t aoff = ((c + 1) & 1) ? G_A1 : G_A0;
            const uint32_t boff = ((c + 1) & 1) ? G_B1 : G_B0;
            #pragma unroll
            for (int i = 0; i < 4; i++) {
                const int id = tid + i * 256;
                const int row = id >> 3;
                const int c4 = (id & 7) * 4;
                cp_async16(smb + (aoff + row * GP + c4) * 4,
                           &g_xt[(size_t)(m0 + row) * EE + k0 + c4]);
                cp_async16(smb + (boff + row * GP + c4) * 4,
                           &Wt[(size_t)(n0 + row) * EE + k0 + c4]);
            }
            CP_COMMIT();
        }

        const float* A = smem + ((c & 1) ? G_A1 : G_A0);
        const float* B = smem + ((c & 1) ? G_B1 : G_B0);

        // A fragments for the whole chunk: [mt][rowhalf][t], t = 2ks(+1)
        float av[2][2][8];
        #pragma unroll
        for (int mt = 0; mt < 2; mt++) {
            const int r = wm * 32 + mt * 16 + lr;
            *(float4*)&av[mt][0][0] = *(const float4*)&A[r * GP + lc * 8];
            *(float4*)&av[mt][0][4] = *(const float4*)&A[r * GP + lc * 8 + 4];
            *(float4*)&av[mt][1][0] = *(const float4*)&A[(r + 8) * GP + lc * 8];
            *(float4*)&av[mt][1][4] = *(const float4*)&A[(r + 8) * GP + lc * 8 + 4];
        }

        #pragma unroll
        for (int j = 0; j < 8; j++) {
            const int nc = wn * 64 + j * 8 + lr;
            float bv4[8];
            *(float4*)&bv4[0] = *(const float4*)&B[nc * GP + lc * 8];
            *(float4*)&bv4[4] = *(const float4*)&B[nc * GP + lc * 8 + 4];
            #pragma unroll
            for (int ks = 0; ks < 4; ks++) {
                mma_tf32(acc[0][j],
                         __float_as_uint(av[0][0][2 * ks]),
                         __float_as_uint(av[0][1][2 * ks]),
                         __float_as_uint(av[0][0][2 * ks + 1]),
                         __float_as_uint(av[0][1][2 * ks + 1]),
                         __float_as_uint(bv4[2 * ks]),
                         __float_as_uint(bv4[2 * ks + 1]));
                mma_tf32(acc[1][j],
                         __float_as_uint(av[1][0][2 * ks]),
                         __float_as_uint(av[1][1][2 * ks]),
                         __float_as_uint(av[1][0][2 * ks + 1]),
                         __float_as_uint(av[1][1][2 * ks + 1]),
                         __float_as_uint(bv4[2 * ks]),
                         __float_as_uint(bv4[2 * ks + 1]));
            }
        }
    }

    // Epilogue: add bias, scale (Q only), round to tf32, scatter to [B,H,T,D]
    #pragma unroll
    for (int mt = 0; mt < 2; mt++) {
        #pragma unroll
        for (int j = 0; j < 8; j++) {
            const int N = n0 + wn * 64 + j * 8 + 2 * lc;
            const int h = N >> 6, d = N & 63;
            const float b0 = __ldg(&bias[N]), b1 = __ldg(&bias[N + 1]);
            #pragma unroll
            for (int half = 0; half < 2; half++) {
                const int M = m0 + wm * 32 + mt * 16 + lr + half * 8;
                const int bb = M >> 11, t = M & (TT - 1);
                float2 o;
                o.x = to_tf32((acc[mt][j][half * 2 + 0] + b0) * osc);
                o.y = to_tf32((acc[mt][j][half * 2 + 1] + b1) * osc);
                *(float2*)&dst[(((size_t)(bb * NH + h) * TT) + t) * DD + d] = o;
            }
        }
    }
}

// ===========================================================================
// Flash attention, prefix-causal band (key j valid iff j <= i + SRC).
// One block = (b, h, 128-query tile). 256 threads (8 warps); warp = 16 rows.
// K/V tiles double-buffered via cp.async (inputs are pre-rounded tf32).
// Online softmax in registers (quad shuffles). Ps overlays Q staging.
// [unchanged from R8]
// ===========================================================================
#define QP 68          // Qs/Ks/Ps pitch (4 mod 32 -> conflict-free row frags)
#define VP 72          // Vs pitch (8 mod 32 -> conflict-free column frags)
#define SM_QS 0        // 128 x QP floats, reused as Ps after Q-frag hoist
#define SM_K0 (128 * QP)              // 8704
#define SM_K1 (SM_K0 + 64 * QP)       // 13056
#define SM_V0 (SM_K1 + 64 * QP)       // 17408
#define SM_V1 (SM_V0 + 64 * VP)       // 22016
#define ATTN_SMEM_FLOATS (SM_V1 + 64 * VP)   // 26624 floats = 106496 B

__global__ __launch_bounds__(256) void attn_kernel(float* __restrict__ out)
{
    extern __shared__ float sm[];
    float* Ps = sm + SM_QS;

    const int qtile = gridDim.x - 1 - blockIdx.x;  // heavy tiles first
    const int h = blockIdx.y;
    const int b = blockIdx.z;
    const int qs = qtile * 128;

    const float* __restrict__ Qb = g_q + (size_t)(b * NH + h) * TT * DD;
    const float* __restrict__ Kb = g_k + (size_t)(b * NH + h) * TT * DD;
    const float* __restrict__ Vb = g_v + (size_t)(b * NH + h) * TT * DD;

    const int tid = threadIdx.x;
    const int lane = tid & 31;
    const int w = tid >> 5;        // warp id 0..7: rows 16w..16w+15
    const int lr = lane >> 2;      // 0..7
    const int lc = lane & 3;       // 0..3

    const uint32_t smb = (uint32_t)__cvta_generic_to_shared(sm);

    // Q cooperative copy: 128 rows x 64 cols; 8 x 16B per thread
    const int qldrow = tid >> 1;            // 0..127
    const int qldc0 = (tid & 1) * 32;       // 0 or 32
    // K/V cooperative copy: 64 rows x 64 cols; 4 x 16B per thread each
    const int kldrow = tid >> 2;            // 0..63
    const int kldc0 = (tid & 3) * 16;       // 0,16,32,48

    // ---- prologue: async-copy Q tile (group), then K/V tile 0 (group) ----
    #pragma unroll
    for (int i = 0; i < 8; i++)
        cp_async16(smb + (uint32_t)(SM_QS + qldrow * QP + qldc0 + i * 4) * 4,
                   &Qb[(size_t)(qs + qldrow) * DD + qldc0 + i * 4]);
    CP_COMMIT();
    #pragma unroll
    for (int i = 0; i < 4; i++) {
        cp_async16(smb + (uint32_t)(SM_K0 + kldrow * QP + kldc0 + i * 4) * 4,
                   &Kb[(size_t)kldrow * DD + kldc0 + i * 4]);
        cp_async16(smb + (uint32_t)(SM_V0 + kldrow * VP + kldc0 + i * 4) * 4,
                   &Vb[(size_t)kldrow * DD + kldc0 + i * 4]);
    }
    CP_COMMIT();

    CP_WAIT(1);          // Q complete (tile0 may still be in flight)
    __syncthreads();

    // hoist Q fragments (constant across KV loop): 8 ksteps x 4 regs
    uint32_t qa[8][4];
    {
        const float* Qs = sm + SM_QS;
        const int r = w * 16 + lr;
        #pragma unroll
        for (int ks8 = 0; ks8 < 8; ks8++) {
            const int kk = ks8 * 8;
            qa[ks8][0] = __float_as_uint(Qs[r * QP + kk + lc]);
            qa[ks8][1] = __float_as_uint(Qs[(r + 8) * QP + kk + lc]);
            qa[ks8][2] = __float_as_uint(Qs[r * QP + kk + lc + 4]);
            qa[ks8][3] = __float_as_uint(Qs[(r + 8) * QP + kk + lc + 4]);
        }
    }

    float o[8][4] = {};
    float m_lo = -1e30f, m_hi = -1e30f, l_lo = 0.0f, l_hi = 0.0f;

    const int ntiles = min(TT / 64, qtile * 2 + 4);

    #pragma unroll 1
    for (int jt = 0; jt < ntiles; jt++) {
        const int kst = jt * 64;
        __syncthreads();   // all warps done with iter jt-1 (incl. buf (jt+1)&1 reads)

        // ---- issue async copies for tile jt+1 into the other buffer ----
        if (jt + 1 < ntiles) {
            const int nk = (jt + 1) * 64;
            const uint32_t koff = ((jt + 1) & 1) ? SM_K1 : SM_K0;
            const uint32_t voff = ((jt + 1) & 1) ? SM_V1 : SM_V0;
            #pragma unroll
            for (int i = 0; i < 4; i++) {
                cp_async16(smb + (koff + kldrow * QP + kldc0 + i * 4) * 4,
                           &Kb[(size_t)(nk + kldrow) * DD + kldc0 + i * 4]);
                cp_async16(smb + (voff + kldrow * VP + kldc0 + i * 4) * 4,
                           &Vb[(size_t)(nk + kldrow) * DD + kldc0 + i * 4]);
            }
            CP_COMMIT();
            CP_WAIT(1);    // tile jt complete; jt+1 may fly
        } else {
            CP_WAIT(0);    // drain: tile jt complete
        }
        __syncthreads();

        const float* Ks = sm + ((jt & 1) ? SM_K1 : SM_K0);
        const float* Vs = sm + ((jt & 1) ? SM_V1 : SM_V0);

        // ---- S = Q @ K^T ----
        float s[8][4] = {};
        #pragma unroll
        for (int ks8 = 0; ks8 < 8; ks8++) {
            const int kk = ks8 * 8;
            #pragma unroll
            for (int j = 0; j < 8; j++) {
                const int key = j * 8 + lr;
                uint32_t b0 = __float_as_uint(Ks[key * QP + kk + lc]);
                uint32_t b1 = __float_as_uint(Ks[key * QP + kk + lc + 4]);
                mma_tf32(s[j], qa[ks8][0], qa[ks8][1], qa[ks8][2], qa[ks8][3], b0, b1);
            }
        }

        // ---- mask (partially-banded tiles only) ----
        if ((kst + 63) > (qs + SRC)) {
            const int rlo = qs + w * 16 + lr;
            #pragma unroll
            for (int j = 0; j < 8; j++) {
                const int c0 = kst + j * 8 + 2 * lc;
                if (c0     > rlo + SRC)     s[j][0] = -1e30f;
                if (c0 + 1 > rlo + SRC)     s[j][1] = -1e30f;
                if (c0     > rlo + 8 + SRC) s[j][2] = -1e30f;
                if (c0 + 1 > rlo + 8 + SRC) s[j][3] = -1e30f;
            }
        }

        // ---- online softmax (rows r=lane>>2 and r+8; quad shuffles) ----
        float mx_lo = -1e30f, mx_hi = -1e30f;
        #pragma unroll
        for (int j = 0; j < 8; j++) {
            mx_lo = fmaxf(mx_lo, fmaxf(s[j][0], s[j][1]));
            mx_hi = fmaxf(mx_hi, fmaxf(s[j][2], s[j][3]));
        }
        #pragma unroll
        for (int off = 1; off <= 2; off <<= 1) {
            mx_lo = fmaxf(mx_lo, __shfl_xor_sync(0xffffffffu, mx_lo, off));
            mx_hi = fmaxf(mx_hi, __shfl_xor_sync(0xffffffffu, mx_hi, off));
        }
        const float mn_lo = fmaxf(m_lo, mx_lo);
        const float mn_hi = fmaxf(m_hi, mx_hi);
        const float al_lo = __expf(m_lo - mn_lo);
        const float al_hi = __expf(m_hi - mn_hi);
        m_lo = mn_lo; m_hi = mn_hi;

        float sum_lo = 0.0f, sum_hi = 0.0f;
        const int prow = w * 16 + lr;
        #pragma unroll
        for (int j = 0; j < 8; j++) {
            float p0 = __expf(s[j][0] - mn_lo);
            float p1 = __expf(s[j][1] - mn_lo);
            float p2 = __expf(s[j][2] - mn_hi);
            float p3 = __expf(s[j][3] - mn_hi);
            sum_lo += p0 + p1;
            sum_hi += p2 + p3;
            float2 vlo = make_float2(to_tf32(p0), to_tf32(p1));
            float2 vhi = make_float2(to_tf32(p2), to_tf32(p3));
            *(float2*)&Ps[prow * QP + j * 8 + 2 * lc] = vlo;
            *(float2*)&Ps[(prow + 8) * QP + j * 8 + 2 * lc] = vhi;
            o[j][0] *= al_lo; o[j][1] *= al_lo;
            o[j][2] *= al_hi; o[j][3] *= al_hi;
        }
        #pragma unroll
        for (int off = 1; off <= 2; off <<= 1) {
            sum_lo += __shfl_xor_sync(0xffffffffu, sum_lo, off);
            sum_hi += __shfl_xor_sync(0xffffffffu, sum_hi, off);
        }
        l_lo = l_lo * al_lo + sum_lo;
        l_hi = l_hi * al_hi + sum_hi;
        __syncwarp();   // Ps rows are warp-private; make stores visible in-warp

        // ---- O += P @ V ----
        #pragma unroll
        for (int ks8 = 0; ks8 < 8; ks8++) {
            const int k0 = ks8 * 8;
            uint32_t a0 = __float_as_uint(Ps[prow * QP + k0 + lc]);
            uint32_t a1 = __float_as_uint(Ps[(prow + 8) * QP + k0 + lc]);
            uint32_t a2 = __float_as_uint(Ps[prow * QP + k0 + lc + 4]);
            uint32_t a3 = __float_as_uint(Ps[(prow + 8) * QP + k0 + lc + 4]);
            #pragma unroll
            for (int j = 0; j < 8; j++) {
                uint32_t b0 = __float_as_uint(Vs[(k0 + lc) * VP + j * 8 + lr]);
                uint32_t b1 = __float_as_uint(Vs[(k0 + lc + 4) * VP + j * 8 + lr]);
                mma_tf32(o[j], a0, a1, a2, a3, b0, b1);
            }
        }
    }

    // ---- finalize: scale by 1/l, write out ----
    const float li_lo = 1.0f / l_lo;
    const float li_hi = 1.0f / l_hi;
    const int t_lo = qs + w * 16 + lr;
    #pragma unroll
    for (int j = 0; j < 8; j++) {
        const int d = j * 8 + 2 * lc;
        float2 v0 = make_float2(o[j][0] * li_lo, o[j][1] * li_lo);
        float2 v1 = make_float2(o[j][2] * li_hi, o[j][3] * li_hi);
        *(float2*)&out[((size_t)(b * TT + t_lo)) * EE + h * DD + d] = v0;
        *(float2*)&out[((size_t)(b * TT + t_lo + 8)) * EE + h * DD + d] = v1;
    }
}

// ---------------------------------------------------------------------------
extern "C" void kernel_launch(void* const* d_in, const int* in_sizes, int n_in,
                              void* d_out, int out_size)
{
    (void)in_sizes; (void)n_in; (void)out_size;
    const float* x  = (const float*)d_in[0];
    const float* Wq = (const float*)d_in[1];
    const float* bq = (const float*)d_in[2];
    const float* Wk = (const float*)d_in[3];
    const float* bk = (const float*)d_in[4];
    const float* Wv = (const float*)d_in[5];
    const float* bv = (const float*)d_in[6];
    float* out = (float*)d_out;

    cudaFuncSetAttribute(qkv_gemm_tc,
                         cudaFuncAttributeMaxDynamicSharedMemorySize,
                         (int)(GEMM_SMEM_FLOATS * sizeof(float)));
    cudaFuncSetAttribute(attn_kernel,
                         cudaFuncAttributeMaxDynamicSharedMemorySize,
                         (int)(ATTN_SMEM_FLOATS * sizeof(float)));

    const int total4 = NX4 + 3 * NW4;               // 1,835,008
    convert_kernel<<<total4 / 256, 256>>>(x, Wq, Wk, Wv);

    dim3 ggrid(EE / 128, (BB * TT) / 128, 3);       // (8, 32, 3)
    qkv_gemm_tc<<<ggrid, 256, GEMM_SMEM_FLOATS * sizeof(float)>>>(bq, bk, bv);

    dim3 agrid(TT / 128, NH, BB);                   // (16, 16, 2)
    attn_kernel<<<agrid, 256, ATTN_SMEM_FLOATS * sizeof(float)>>>(out);
}

// round 10
// speedup vs baseline: 1.9018x; 1.0391x over previous
#include <cuda_runtime.h>
#include <math.h>
#include <cstdint>

#define BB 2
#define NH 16
#define TT 2048
#define DD 64
#define EE 1024
#define SRC 128

// Scratch (no cudaMalloc allowed).
// g_q/g_k/g_v: projected tensors, tf32-rounded (Q pre-scaled by 1/8), [B,H,T,D].
// g_xt / g_wt: tf32-rounded, 32-chunk fragment-permuted copies of x and W.
__device__ float g_q[BB * NH * TT * DD];
__device__ float g_k[BB * NH * TT * DD];
__device__ float g_v[BB * NH * TT * DD];
__device__ float g_xt[BB * TT * EE];
__device__ float g_wt[3][EE * EE];

__device__ __forceinline__ float to_tf32(float f) {
    float r;
    asm("cvt.rna.tf32.f32 %0, %1;" : "=f"(r) : "f"(f));
    return r;
}

// D += A(16x8) * B(8x8), tf32 inputs (as b32 regs), fp32 accum.
__device__ __forceinline__ void mma_tf32(
    float* d, uint32_t a0, uint32_t a1, uint32_t a2, uint32_t a3,
    uint32_t b0, uint32_t b1)
{
    asm volatile(
        "mma.sync.aligned.m16n8k8.row.col.f32.tf32.tf32.f32 "
        "{%0,%1,%2,%3}, {%4,%5,%6,%7}, {%8,%9}, {%0,%1,%2,%3};"
        : "+f"(d[0]), "+f"(d[1]), "+f"(d[2]), "+f"(d[3])
        : "r"(a0), "r"(a1), "r"(a2), "r"(a3), "r"(b0), "r"(b1));
}

__device__ __forceinline__ void cp_async16(uint32_t smem_addr, const void* gptr) {
    asm volatile("cp.async.cg.shared.global [%0], [%1], 16;"
                 :: "r"(smem_addr), "l"(gptr));
}
#define CP_COMMIT() asm volatile("cp.async.commit_group;" ::: "memory")
#define CP_WAIT(N)  asm volatile("cp.async.wait_group %0;" :: "n"(N) : "memory")

// ===========================================================================
// Convert kernel: tf32-round x and Wq/Wk/Wv into g_xt / g_wt with each
// 32-column chunk permuted fragment-major: c'(k) = (k%4)*8 + k/4.
// ===========================================================================
#define NX4 ((BB * TT * EE) / 4)   // 1048576
#define NW4 ((EE * EE) / 4)        // 262144

__global__ __launch_bounds__(256) void convert_kernel(
    const float* __restrict__ x,
    const float* __restrict__ Wq,
    const float* __restrict__ Wk,
    const float* __restrict__ Wv)
{
    const int idx = blockIdx.x * blockDim.x + threadIdx.x;
    const float* __restrict__ src;
    float* __restrict__ dst;
    int li;
    if (idx < NX4) {
        src = x; dst = g_xt; li = idx;
    } else {
        const int t = idx - NX4;
        const int z = t / NW4;
        li = t - z * NW4;
        src = (z == 0) ? Wq : (z == 1) ? Wk : Wv;
        dst = g_wt[z];
    }
    const float4 v = ((const float4*)src)[li];
    const int f = li * 4;
    const int row = f >> 10;
    const int col = f & 1023;
    const int ch = col >> 5, kc = col & 31;          // kc % 4 == 0
    const int base = (row << 10) | (ch << 5) | (kc >> 2);
    dst[base + 0]  = to_tf32(v.x);
    dst[base + 8]  = to_tf32(v.y);
    dst[base + 16] = to_tf32(v.z);
    dst[base + 24] = to_tf32(v.w);
}

// ===========================================================================
// QKV projection: y = x @ W^T + b, scattered into [B,H,T,D].  tf32 mma.sync.
// Operands pre-rounded + fragment-permuted; cp.async double-buffered;
// fragment reads are conflict-free LDS.128.  [unchanged from R9]
// ===========================================================================
#define GP 36                 // smem row pitch (floats); 144B, 16B-aligned
#define GBUF (128 * GP)       // 4608 floats per tile buffer
#define G_A0 0
#define G_A1 GBUF
#define G_B0 (2 * GBUF)
#define G_B1 (3 * GBUF)
#define GEMM_SMEM_FLOATS (4 * GBUF)   // 18432 floats = 73728 B

__global__ __launch_bounds__(256, 2) void qkv_gemm_tc(
    const float* __restrict__ bq,
    const float* __restrict__ bk,
    const float* __restrict__ bv)
{
    extern __shared__ float smem[];

    const int z = blockIdx.z;
    const float* __restrict__ Wt   = g_wt[z];
    const float* __restrict__ bias = (z == 0) ? bq : (z == 1) ? bk : bv;
    float* __restrict__ dst        = (z == 0) ? g_q : (z == 1) ? g_k : g_v;
    const float osc = (z == 0) ? 0.125f : 1.0f;

    const int m0 = blockIdx.y * 128;
    const int n0 = blockIdx.x * 128;
    const int tid = threadIdx.x;
    const int lane = tid & 31;
    const int wid = tid >> 5;
    const int wm = wid & 3;        // 0..3 : M warp (32 rows)
    const int wn = wid >> 2;       // 0..1 : N warp (64 cols)
    const int lr = lane >> 2;      // 0..7
    const int lc = lane & 3;       // 0..3

    const uint32_t smb = (uint32_t)__cvta_generic_to_shared(smem);

    #pragma unroll
    for (int i = 0; i < 4; i++) {
        const int id = tid + i * 256;
        const int row = id >> 3;
        const int c4 = (id & 7) * 4;
        cp_async16(smb + (uint32_t)(G_A0 + row * GP + c4) * 4,
                   &g_xt[(size_t)(m0 + row) * EE + c4]);
        cp_async16(smb + (uint32_t)(G_B0 + row * GP + c4) * 4,
                   &Wt[(size_t)(n0 + row) * EE + c4]);
    }
    CP_COMMIT();

    float acc[2][8][4] = {};

    #pragma unroll 1
    for (int c = 0; c < EE / 32; c++) {
        CP_WAIT(0);
        __syncthreads();

        if (c + 1 < EE / 32) {
            const int k0 = (c + 1) * 32;
            const uint32_t aoff = ((c + 1) & 1) ? G_A1 : G_A0;
            const uint32_t boff = ((c + 1) & 1) ? G_B1 : G_B0;
            #pragma unroll
            for (int i = 0; i < 4; i++) {
                const int id = tid + i * 256;
                const int row = id >> 3;
                const int c4 = (id & 7) * 4;
                cp_async16(smb + (aoff + row * GP + c4) * 4,
                           &g_xt[(size_t)(m0 + row) * EE + k0 + c4]);
                cp_async16(smb + (boff + row * GP + c4) * 4,
                           &Wt[(size_t)(n0 + row) * EE + k0 + c4]);
            }
            CP_COMMIT();
        }

        const float* A = smem + ((c & 1) ? G_A1 : G_A0);
        const float* B = smem + ((c & 1) ? G_B1 : G_B0);

        float av[2][2][8];
        #pragma unroll
        for (int mt = 0; mt < 2; mt++) {
            const int r = wm * 32 + mt * 16 + lr;
            *(float4*)&av[mt][0][0] = *(const float4*)&A[r * GP + lc * 8];
            *(float4*)&av[mt][0][4] = *(const float4*)&A[r * GP + lc * 8 + 4];
            *(float4*)&av[mt][1][0] = *(const float4*)&A[(r + 8) * GP + lc * 8];
            *(float4*)&av[mt][1][4] = *(const float4*)&A[(r + 8) * GP + lc * 8 + 4];
        }

        #pragma unroll
        for (int j = 0; j < 8; j++) {
            const int nc = wn * 64 + j * 8 + lr;
            float bv4[8];
            *(float4*)&bv4[0] = *(const float4*)&B[nc * GP + lc * 8];
            *(float4*)&bv4[4] = *(const float4*)&B[nc * GP + lc * 8 + 4];
            #pragma unroll
            for (int ks = 0; ks < 4; ks++) {
                mma_tf32(acc[0][j],
                         __float_as_uint(av[0][0][2 * ks]),
                         __float_as_uint(av[0][1][2 * ks]),
                         __float_as_uint(av[0][0][2 * ks + 1]),
                         __float_as_uint(av[0][1][2 * ks + 1]),
                         __float_as_uint(bv4[2 * ks]),
                         __float_as_uint(bv4[2 * ks + 1]));
                mma_tf32(acc[1][j],
                         __float_as_uint(av[1][0][2 * ks]),
                         __float_as_uint(av[1][1][2 * ks]),
                         __float_as_uint(av[1][0][2 * ks + 1]),
                         __float_as_uint(av[1][1][2 * ks + 1]),
                         __float_as_uint(bv4[2 * ks]),
                         __float_as_uint(bv4[2 * ks + 1]));
            }
        }
    }

    #pragma unroll
    for (int mt = 0; mt < 2; mt++) {
        #pragma unroll
        for (int j = 0; j < 8; j++) {
            const int N = n0 + wn * 64 + j * 8 + 2 * lc;
            const int h = N >> 6, d = N & 63;
            const float b0 = __ldg(&bias[N]), b1 = __ldg(&bias[N + 1]);
            #pragma unroll
            for (int half = 0; half < 2; half++) {
                const int M = m0 + wm * 32 + mt * 16 + lr + half * 8;
                const int bb = M >> 11, t = M & (TT - 1);
                float2 o;
                o.x = to_tf32((acc[mt][j][half * 2 + 0] + b0) * osc);
                o.y = to_tf32((acc[mt][j][half * 2 + 1] + b1) * osc);
                *(float2*)&dst[(((size_t)(bb * NH + h) * TT) + t) * DD + d] = o;
            }
        }
    }
}

// ===========================================================================
// Flash attention, prefix-causal band (key j valid iff j <= i + SRC).
// One block = (b, h, 256-query tile). 512 threads (16 warps); warp = 16 rows.
// Each 64-key K/V tile now serves 256 query rows (staging traffic and
// barrier count per q-row halved vs R8/R9). K/V double-buffered cp.async.
// Online softmax in registers (quad shuffles). Ps overlays Q staging.
// ===========================================================================
#define QROWS 256
#define QP 68          // Qs/Ks/Ps pitch (4 mod 32 -> conflict-free row frags)
#define VP 72          // Vs pitch (8 mod 32 -> conflict-free column frags)
#define SM_QS 0        // QROWS x QP floats, reused as Ps after Q-frag hoist
#define SM_K0 (QROWS * QP)            // 17408
#define SM_K1 (SM_K0 + 64 * QP)       // 21760
#define SM_V0 (SM_K1 + 64 * QP)       // 26112
#define SM_V1 (SM_V0 + 64 * VP)       // 30720
#define ATTN_SMEM_FLOATS (SM_V1 + 64 * VP)   // 35328 floats = 141312 B

__global__ __launch_bounds__(512, 1) void attn_kernel(float* __restrict__ out)
{
    extern __shared__ float sm[];
    float* Ps = sm + SM_QS;

    const int qtile = gridDim.x - 1 - blockIdx.x;  // heavy tiles first
    const int h = blockIdx.y;
    const int b = blockIdx.z;
    const int qs = qtile * QROWS;

    const float* __restrict__ Qb = g_q + (size_t)(b * NH + h) * TT * DD;
    const float* __restrict__ Kb = g_k + (size_t)(b * NH + h) * TT * DD;
    const float* __restrict__ Vb = g_v + (size_t)(b * NH + h) * TT * DD;

    const int tid = threadIdx.x;
    const int lane = tid & 31;
    const int w = tid >> 5;        // warp id 0..15: rows 16w..16w+15
    const int lr = lane >> 2;      // 0..7
    const int lc = lane & 3;       // 0..3

    const uint32_t smb = (uint32_t)__cvta_generic_to_shared(sm);

    // Q cooperative copy: 256 rows x 64 cols = 4096 f4; 8 per thread
    const int qldrow = tid >> 1;            // 0..255
    const int qldc0 = (tid & 1) * 32;       // 0 or 32
    // K/V cooperative copy: 64 rows x 64 cols = 1024 f4; 2 per thread each
    const int kldrow = tid >> 3;            // 0..63
    const int kldc0 = (tid & 7) * 8;        // 0,8,...,56 (two f4: +0, +4)

    // ---- prologue: async-copy Q tile (group), then K/V tile 0 (group) ----
    #pragma unroll
    for (int i = 0; i < 8; i++)
        cp_async16(smb + (uint32_t)(SM_QS + qldrow * QP + qldc0 + i * 4) * 4,
                   &Qb[(size_t)(qs + qldrow) * DD + qldc0 + i * 4]);
    CP_COMMIT();
    #pragma unroll
    for (int i = 0; i < 2; i++) {
        cp_async16(smb + (uint32_t)(SM_K0 + kldrow * QP + kldc0 + i * 4) * 4,
                   &Kb[(size_t)kldrow * DD + kldc0 + i * 4]);
        cp_async16(smb + (uint32_t)(SM_V0 + kldrow * VP + kldc0 + i * 4) * 4,
                   &Vb[(size_t)kldrow * DD + kldc0 + i * 4]);
    }
    CP_COMMIT();

    CP_WAIT(1);          // Q complete (tile0 may still be in flight)
    __syncthreads();

    // hoist Q fragments (constant across KV loop): 8 ksteps x 4 regs
    uint32_t qa[8][4];
    {
        const float* Qs = sm + SM_QS;
        const int r = w * 16 + lr;
        #pragma unroll
        for (int ks8 = 0; ks8 < 8; ks8++) {
            const int kk = ks8 * 8;
            qa[ks8][0] = __float_as_uint(Qs[r * QP + kk + lc]);
            qa[ks8][1] = __float_as_uint(Qs[(r + 8) * QP + kk + lc]);
            qa[ks8][2] = __float_as_uint(Qs[r * QP + kk + lc + 4]);
            qa[ks8][3] = __float_as_uint(Qs[(r + 8) * QP + kk + lc + 4]);
        }
    }

    float o[8][4] = {};
    float m_lo = -1e30f, m_hi = -1e30f, l_lo = 0.0f, l_hi = 0.0f;

    const int ntiles = min(TT / 64, qtile * 4 + 6);

    #pragma unroll 1
    for (int jt = 0; jt < ntiles; jt++) {
        const int kst = jt * 64;
        __syncthreads();   // all warps done with iter jt-1 (incl. buf (jt+1)&1 reads)

        // ---- issue async copies for tile jt+1 into the other buffer ----
        if (jt + 1 < ntiles) {
            const int nk = (jt + 1) * 64;
            const uint32_t koff = ((jt + 1) & 1) ? SM_K1 : SM_K0;
            const uint32_t voff = ((jt + 1) & 1) ? SM_V1 : SM_V0;
            #pragma unroll
            for (int i = 0; i < 2; i++) {
                cp_async16(smb + (koff + kldrow * QP + kldc0 + i * 4) * 4,
                           &Kb[(size_t)(nk + kldrow) * DD + kldc0 + i * 4]);
                cp_async16(smb + (voff + kldrow * VP + kldc0 + i * 4) * 4,
                           &Vb[(size_t)(nk + kldrow) * DD + kldc0 + i * 4]);
            }
            CP_COMMIT();
            CP_WAIT(1);    // tile jt complete; jt+1 may fly
        } else {
            CP_WAIT(0);    // drain: tile jt complete
        }
        __syncthreads();

        const float* Ks = sm + ((jt & 1) ? SM_K1 : SM_K0);
        const float* Vs = sm + ((jt & 1) ? SM_V1 : SM_V0);

        // ---- S = Q @ K^T ----
        float s[8][4] = {};
        #pragma unroll
        for (int ks8 = 0; ks8 < 8; ks8++) {
            const int kk = ks8 * 8;
            #pragma unroll
            for (int j = 0; j < 8; j++) {
                const int key = j * 8 + lr;
                uint32_t b0 = __float_as_uint(Ks[key * QP + kk + lc]);
                uint32_t b1 = __float_as_uint(Ks[key * QP + kk + lc + 4]);
                mma_tf32(s[j], qa[ks8][0], qa[ks8][1], qa[ks8][2], qa[ks8][3], b0, b1);
            }
        }

        // ---- mask (partially-banded tiles only; per-row check inside) ----
        if ((kst + 63) > (qs + SRC)) {
            const int rlo = qs + w * 16 + lr;
            #pragma unroll
            for (int j = 0; j < 8; j++) {
                const int c0 = kst + j * 8 + 2 * lc;
                if (c0     > rlo + SRC)     s[j][0] = -1e30f;
                if (c0 + 1 > rlo + SRC)     s[j][1] = -1e30f;
                if (c0     > rlo + 8 + SRC) s[j][2] = -1e30f;
                if (c0 + 1 > rlo + 8 + SRC) s[j][3] = -1e30f;
            }
        }

        // ---- online softmax (rows r=lane>>2 and r+8; quad shuffles) ----
        float mx_lo = -1e30f, mx_hi = -1e30f;
        #pragma unroll
        for (int j = 0; j < 8; j++) {
            mx_lo = fmaxf(mx_lo, fmaxf(s[j][0], s[j][1]));
            mx_hi = fmaxf(mx_hi, fmaxf(s[j][2], s[j][3]));
        }
        #pragma unroll
        for (int off = 1; off <= 2; off <<= 1) {
            mx_lo = fmaxf(mx_lo, __shfl_xor_sync(0xffffffffu, mx_lo, off));
            mx_hi = fmaxf(mx_hi, __shfl_xor_sync(0xffffffffu, mx_hi, off));
        }
        const float mn_lo = fmaxf(m_lo, mx_lo);
        const float mn_hi = fmaxf(m_hi, mx_hi);
        const float al_lo = __expf(m_lo - mn_lo);
        const float al_hi = __expf(m_hi - mn_hi);
        m_lo = mn_lo; m_hi = mn_hi;

        float sum_lo = 0.0f, sum_hi = 0.0f;
        const int prow = w * 16 + lr;
        #pragma unroll
        for (int j = 0; j < 8; j++) {
            float p0 = __expf(s[j][0] - mn_lo);
            float p1 = __expf(s[j][1] - mn_lo);
            float p2 = __expf(s[j][2] - mn_hi);
            float p3 = __expf(s[j][3] - mn_hi);
            sum_lo += p0 + p1;
            sum_hi += p2 + p3;
            float2 vlo = make_float2(to_tf32(p0), to_tf32(p1));
            float2 vhi = make_float2(to_tf32(p2), to_tf32(p3));
            *(float2*)&Ps[prow * QP + j * 8 + 2 * lc] = vlo;
            *(float2*)&Ps[(prow + 8) * QP + j * 8 + 2 * lc] = vhi;
            o[j][0] *= al_lo; o[j][1] *= al_lo;
            o[j][2] *= al_hi; o[j][3] *= al_hi;
        }
        #pragma unroll
        for (int off = 1; off <= 2; off <<= 1) {
            sum_lo += __shfl_xor_sync(0xffffffffu, sum_lo, off);
            sum_hi += __shfl_xor_sync(0xffffffffu, sum_hi, off);
        }
        l_lo = l_lo * al_lo + sum_lo;
        l_hi = l_hi * al_hi + sum_hi;
        __syncwarp();   // Ps rows are warp-private; make stores visible in-warp

        // ---- O += P @ V ----
        #pragma unroll
        for (int ks8 = 0; ks8 < 8; ks8++) {
            const int k0 = ks8 * 8;
            uint32_t a0 = __float_as_uint(Ps[prow * QP + k0 + lc]);
            uint32_t a1 = __float_as_uint(Ps[(prow + 8) * QP + k0 + lc]);
            uint32_t a2 = __float_as_uint(Ps[prow * QP + k0 + lc + 4]);
            uint32_t a3 = __float_as_uint(Ps[(prow + 8) * QP + k0 + lc + 4]);
            #pragma unroll
            for (int j = 0; j < 8; j++) {
                uint32_t b0 = __float_as_uint(Vs[(k0 + lc) * VP + j * 8 + lr]);
                uint32_t b1 = __float_as_uint(Vs[(k0 + lc + 4) * VP + j * 8 + lr]);
                mma_tf32(o[j], a0, a1, a2, a3, b0, b1);
            }
        }
    }

    // ---- finalize: scale by 1/l, write out ----
    const float li_lo = 1.0f / l_lo;
    const float li_hi = 1.0f / l_hi;
    const int t_lo = qs + w * 16 + lr;
    #pragma unroll
    for (int j = 0; j < 8; j++) {
        const int d = j * 8 + 2 * lc;
        float2 v0 = make_float2(o[j][0] * li_lo, o[j][1] * li_lo);
        float2 v1 = make_float2(o[j][2] * li_hi, o[j][3] * li_hi);
        *(float2*)&out[((size_t)(b * TT + t_lo)) * EE + h * DD + d] = v0;
        *(float2*)&out[((size_t)(b * TT + t_lo + 8)) * EE + h * DD + d] = v1;
    }
}

// ---------------------------------------------------------------------------
extern "C" void kernel_launch(void* const* d_in, const int* in_sizes, int n_in,
                              void* d_out, int out_size)
{
    (void)in_sizes; (void)n_in; (void)out_size;
    const float* x  = (const float*)d_in[0];
    const float* Wq = (const float*)d_in[1];
    const float* bq = (const float*)d_in[2];
    const float* Wk = (const float*)d_in[3];
    const float* bk = (const float*)d_in[4];
    const float* Wv = (const float*)d_in[5];
    const float* bv = (const float*)d_in[6];
    float* out = (float*)d_out;

    cudaFuncSetAttribute(qkv_gemm_tc,
                         cudaFuncAttributeMaxDynamicSharedMemorySize,
                         (int)(GEMM_SMEM_FLOATS * sizeof(float)));
    cudaFuncSetAttribute(attn_kernel,
                         cudaFuncAttributeMaxDynamicSharedMemorySize,
                         (int)(ATTN_SMEM_FLOATS * sizeof(float)));

    const int total4 = NX4 + 3 * NW4;               // 1,835,008
    convert_kernel<<<total4 / 256, 256>>>(x, Wq, Wk, Wv);

    dim3 ggrid(EE / 128, (BB * TT) / 128, 3);       // (8, 32, 3)
    qkv_gemm_tc<<<ggrid, 256, GEMM_SMEM_FLOATS * sizeof(float)>>>(bq, bk, bv);

    dim3 agrid(TT / QROWS, NH, BB);                 // (8, 16, 2)
    attn_kernel<<<agrid, 512, ATTN_SMEM_FLOATS * sizeof(float)>>>(out);
}

// round 11
// speedup vs baseline: 3.9600x; 2.0822x over previous
#include <cuda_runtime.h>
#include <cuda_fp16.h>
#include <math.h>
#include <cstdint>

#define BB 2
#define NH 16
#define TT 2048
#define DD 64
#define EE 1024
#define SRC 128

// Scratch (no cudaMalloc allowed). All fp16 (Q pre-scaled by 1/8).
__device__ __half g_qh[BB * NH * TT * DD];
__device__ __half g_kh[BB * NH * TT * DD];
__device__ __half g_vh[BB * NH * TT * DD];
__device__ __half g_xh[BB * TT * EE];
__device__ __half g_wh[3][EE * EE];

__device__ __forceinline__ uint32_t ph2(float lo, float hi) {
    __half2 h = __floats2half2_rn(lo, hi);
    return *(uint32_t*)&h;
}

// D += A(16x16) * B(16x8), fp16 inputs, fp32 accum.
__device__ __forceinline__ void mma_f16(
    float* d, uint32_t a0, uint32_t a1, uint32_t a2, uint32_t a3,
    uint32_t b0, uint32_t b1)
{
    asm volatile(
        "mma.sync.aligned.m16n8k16.row.col.f32.f16.f16.f32 "
        "{%0,%1,%2,%3}, {%4,%5,%6,%7}, {%8,%9}, {%0,%1,%2,%3};"
        : "+f"(d[0]), "+f"(d[1]), "+f"(d[2]), "+f"(d[3])
        : "r"(a0), "r"(a1), "r"(a2), "r"(a3), "r"(b0), "r"(b1));
}

__device__ __forceinline__ void ldm4(uint32_t* r, uint32_t a) {
    asm volatile("ldmatrix.sync.aligned.m8n8.x4.shared.b16 {%0,%1,%2,%3}, [%4];"
        : "=r"(r[0]), "=r"(r[1]), "=r"(r[2]), "=r"(r[3]) : "r"(a));
}
__device__ __forceinline__ void ldm4t(uint32_t* r, uint32_t a) {
    asm volatile("ldmatrix.sync.aligned.m8n8.x4.trans.shared.b16 {%0,%1,%2,%3}, [%4];"
        : "=r"(r[0]), "=r"(r[1]), "=r"(r[2]), "=r"(r[3]) : "r"(a));
}

__device__ __forceinline__ void cp_async16(uint32_t smem_addr, const void* gptr) {
    asm volatile("cp.async.cg.shared.global [%0], [%1], 16;"
                 :: "r"(smem_addr), "l"(gptr));
}
#define CP_COMMIT() asm volatile("cp.async.commit_group;" ::: "memory")
#define CP_WAIT(N)  asm volatile("cp.async.wait_group %0;" :: "n"(N) : "memory")

// ===========================================================================
// Convert kernel: plain fp32 -> fp16 of x and Wq/Wk/Wv (no permute needed;
// ldmatrix handles fragment gathering).
// ===========================================================================
#define NX4 ((BB * TT * EE) / 4)   // 1048576
#define NW4 ((EE * EE) / 4)        // 262144

__global__ __launch_bounds__(256) void convert_kernel(
    const float* __restrict__ x,
    const float* __restrict__ Wq,
    const float* __restrict__ Wk,
    const float* __restrict__ Wv)
{
    const int idx = blockIdx.x * blockDim.x + threadIdx.x;
    const float* __restrict__ src;
    __half* __restrict__ dst;
    int li;
    if (idx < NX4) {
        src = x; dst = g_xh; li = idx;
    } else {
        const int t = idx - NX4;
        const int z = t / NW4;
        li = t - z * NW4;
        src = (z == 0) ? Wq : (z == 1) ? Wk : Wv;
        dst = g_wh[z];
    }
    const float4 v = ((const float4*)src)[li];
    uint2 o;
    o.x = ph2(v.x, v.y);
    o.y = ph2(v.z, v.w);
    ((uint2*)dst)[li] = o;
}

// ===========================================================================
// QKV projection: y = x @ W^T + b -> fp16 [B,H,T,D].  fp16 m16n8k16 mma.
// Block tile 128x128, 256 threads (8 warps as 4Mx2N; warp tile 32x64).
// 64-K chunks, double-buffered cp.async; fragments via ldmatrix.x4.
// Row pitch 144B -> ldmatrix phases conflict-free. grid = (8, 32, 3)
// ===========================================================================
#define GROWB 144                  // bytes per smem row (64 halfs + pad)
#define GBUF_B (128 * GROWB)       // 18432 B per tile buffer
#define G_A0 0u
#define G_A1 18432u
#define G_B0 36864u
#define G_B1 55296u
#define GEMM_SMEM_BYTES 73728

__global__ __launch_bounds__(256, 2) void qkv_gemm_tc(
    const float* __restrict__ bq,
    const float* __restrict__ bk,
    const float* __restrict__ bv)
{
    extern __shared__ char smc[];

    const int z = blockIdx.z;
    const __half* __restrict__ Wt  = g_wh[z];
    const float* __restrict__ bias = (z == 0) ? bq : (z == 1) ? bk : bv;
    __half* __restrict__ dst       = (z == 0) ? g_qh : (z == 1) ? g_kh : g_vh;
    const float osc = (z == 0) ? 0.125f : 1.0f;

    const int m0 = blockIdx.y * 128;
    const int n0 = blockIdx.x * 128;
    const int tid = threadIdx.x;
    const int lane = tid & 31;
    const int wid = tid >> 5;
    const int wm = wid & 3;        // 0..3 : M warp (32 rows)
    const int wn = wid >> 2;       // 0..1 : N warp (64 cols)
    const int lr = lane >> 2;      // 0..7
    const int lc = lane & 3;       // 0..3

    const uint32_t smb = (uint32_t)__cvta_generic_to_shared(smc);

    // ldmatrix per-lane address pieces
    const int a_row = lane & 15;             // A-type x4: rows 0..15
    const int a_off = (lane >> 4) * 16;      // +16B for k 8..15 tiles
    const int b_row = ((lane >> 4) * 8) + (lane & 7);   // B-type: j-pair rows
    const int b_off = ((lane >> 3) & 1) * 16;

    // cp.async mapping: 128 rows x 8 x16B chunks = 1024; 4 per thread
    // prologue: chunk 0 -> buffer 0
    #pragma unroll
    for (int i = 0; i < 4; i++) {
        const int id = tid + i * 256;
        const int row = id >> 3;
        const int ch = id & 7;
        cp_async16(smb + G_A0 + row * GROWB + ch * 16,
                   &g_xh[(size_t)(m0 + row) * EE + ch * 8]);
        cp_async16(smb + G_B0 + row * GROWB + ch * 16,
                   &Wt[(size_t)(n0 + row) * EE + ch * 8]);
    }
    CP_COMMIT();

    float acc[2][8][4] = {};

    #pragma unroll 1
    for (int c = 0; c < EE / 64; c++) {
        CP_WAIT(0);
        __syncthreads();

        if (c + 1 < EE / 64) {
            const int k0 = (c + 1) * 64;
            const uint32_t aoff = ((c + 1) & 1) ? G_A1 : G_A0;
            const uint32_t boff = ((c + 1) & 1) ? G_B1 : G_B0;
            #pragma unroll
            for (int i = 0; i < 4; i++) {
                const int id = tid + i * 256;
                const int row = id >> 3;
                const int ch = id & 7;
                cp_async16(smb + aoff + row * GROWB + ch * 16,
                           &g_xh[(size_t)(m0 + row) * EE + k0 + ch * 8]);
                cp_async16(smb + boff + row * GROWB + ch * 16,
                           &Wt[(size_t)(n0 + row) * EE + k0 + ch * 8]);
            }
            CP_COMMIT();
        }

        const uint32_t A = smb + ((c & 1) ? G_A1 : G_A0);
        const uint32_t B = smb + ((c & 1) ? G_B1 : G_B0);

        // hoist A fragments for all 4 ksteps (2 mt x 4 ks x 4 regs)
        uint32_t av[2][4][4];
        #pragma unroll
        for (int mt = 0; mt < 2; mt++)
            #pragma unroll
            for (int ks = 0; ks < 4; ks++)
                ldm4(av[mt][ks],
                     A + (wm * 32 + mt * 16 + a_row) * GROWB + ks * 32 + a_off);

        #pragma unroll
        for (int ks = 0; ks < 4; ks++) {
            #pragma unroll
            for (int jp = 0; jp < 4; jp++) {
                uint32_t bf[4];
                ldm4(bf, B + (wn * 64 + jp * 16 + b_row) * GROWB + ks * 32 + b_off);
                mma_f16(acc[0][2 * jp],     av[0][ks][0], av[0][ks][1], av[0][ks][2], av[0][ks][3], bf[0], bf[1]);
                mma_f16(acc[0][2 * jp + 1], av[0][ks][0], av[0][ks][1], av[0][ks][2], av[0][ks][3], bf[2], bf[3]);
                mma_f16(acc[1][2 * jp],     av[1][ks][0], av[1][ks][1], av[1][ks][2], av[1][ks][3], bf[0], bf[1]);
                mma_f16(acc[1][2 * jp + 1], av[1][ks][0], av[1][ks][1], av[1][ks][2], av[1][ks][3], bf[2], bf[3]);
            }
        }
    }

    // Epilogue: add bias, scale (Q only), convert fp16, scatter to [B,H,T,D]
    #pragma unroll
    for (int mt = 0; mt < 2; mt++) {
        #pragma unroll
        for (int j = 0; j < 8; j++) {
            const int N = n0 + wn * 64 + j * 8 + 2 * lc;
            const int h = N >> 6, d = N & 63;
            const float b0 = __ldg(&bias[N]), b1 = __ldg(&bias[N + 1]);
            #pragma unroll
            for (int half_ = 0; half_ < 2; half_++) {
                const int M = m0 + wm * 32 + mt * 16 + lr + half_ * 8;
                const int bb = M >> 11, t = M & (TT - 1);
                const uint32_t hv = ph2((acc[mt][j][half_ * 2 + 0] + b0) * osc,
                                        (acc[mt][j][half_ * 2 + 1] + b1) * osc);
                *(uint32_t*)&dst[(((size_t)(bb * NH + h) * TT) + t) * DD + d] = hv;
            }
        }
    }
}

// ===========================================================================
// Flash attention, prefix-causal band (key j valid iff j <= i + SRC).
// One block = (b, h, 256-query tile). 512 threads (16 warps); warp = 16 rows.
// fp16 m16n8k16; fragments via ldmatrix (trans for V). K/V double-buffered
// cp.async. Online softmax in registers. Ps (fp16) overlays Q staging.
// ===========================================================================
#define QROWS 256
#define AROWB 144                     // bytes per smem row (64 halfs + pad)
#define AS_QS 0u                      // 256 rows -> 36864 B (reused as Ps)
#define AS_K0 36864u
#define AS_K1 46080u
#define AS_V0 55296u
#define AS_V1 64512u
#define ATTN_SMEM_BYTES 73728

__global__ __launch_bounds__(512, 1) void attn_kernel(float* __restrict__ out)
{
    extern __shared__ char smc[];
    __half* Psh = (__half*)smc;      // rows of 72 halfs (144B pitch)

    const int qtile = gridDim.x - 1 - blockIdx.x;  // heavy tiles first
    const int h = blockIdx.y;
    const int b = blockIdx.z;
    const int qs = qtile * QROWS;

    const __half* __restrict__ Qb = g_qh + (size_t)(b * NH + h) * TT * DD;
    const __half* __restrict__ Kb = g_kh + (size_t)(b * NH + h) * TT * DD;
    const __half* __restrict__ Vb = g_vh + (size_t)(b * NH + h) * TT * DD;

    const int tid = threadIdx.x;
    const int lane = tid & 31;
    const int w = tid >> 5;        // warp id 0..15: rows 16w..16w+15
    const int lr = lane >> 2;      // 0..7
    const int lc = lane & 3;       // 0..3

    const uint32_t smb = (uint32_t)__cvta_generic_to_shared(smc);

    const int a_row = lane & 15;
    const int a_off = (lane >> 4) * 16;
    const int b_row = ((lane >> 4) * 8) + (lane & 7);
    const int b_off = ((lane >> 3) & 1) * 16;

    // Q copy: 256 rows x 8 chunks = 2048; 4 per thread
    #pragma unroll
    for (int i = 0; i < 4; i++) {
        const int id = tid + i * 512;
        const int row = id >> 3;
        const int ch = id & 7;
        cp_async16(smb + AS_QS + row * AROWB + ch * 16,
                   &Qb[(size_t)(qs + row) * DD + ch * 8]);
    }
    CP_COMMIT();
    // K/V tile 0: 64 rows x 8 chunks = 512; 1 per thread each
    {
        const int row = tid >> 3;
        const int ch = tid & 7;
        cp_async16(smb + AS_K0 + row * AROWB + ch * 16, &Kb[(size_t)row * DD + ch * 8]);
        cp_async16(smb + AS_V0 + row * AROWB + ch * 16, &Vb[(size_t)row * DD + ch * 8]);
    }
    CP_COMMIT();

    CP_WAIT(1);          // Q landed (tile0 may still be in flight)
    __syncthreads();

    // hoist Q fragments: 4 ksteps x 4 regs
    uint32_t qa[4][4];
    #pragma unroll
    for (int ks = 0; ks < 4; ks++)
        ldm4(qa[ks], smb + AS_QS + (w * 16 + a_row) * AROWB + ks * 32 + a_off);

    float o[8][4] = {};
    float m_lo = -1e30f, m_hi = -1e30f, l_lo = 0.0f, l_hi = 0.0f;

    const int ntiles = min(TT / 64, qtile * 4 + 6);

    #pragma unroll 1
    for (int jt = 0; jt < ntiles; jt++) {
        const int kst = jt * 64;
        __syncthreads();   // all warps done with iter jt-1

        if (jt + 1 < ntiles) {
            const int nk = (jt + 1) * 64;
            const uint32_t koff = ((jt + 1) & 1) ? AS_K1 : AS_K0;
            const uint32_t voff = ((jt + 1) & 1) ? AS_V1 : AS_V0;
            const int row = tid >> 3;
            const int ch = tid & 7;
            cp_async16(smb + koff + row * AROWB + ch * 16,
                       &Kb[(size_t)(nk + row) * DD + ch * 8]);
            cp_async16(smb + voff + row * AROWB + ch * 16,
                       &Vb[(size_t)(nk + row) * DD + ch * 8]);
            CP_COMMIT();
            CP_WAIT(1);    // tile jt complete; jt+1 may fly
        } else {
            CP_WAIT(0);
        }
        __syncthreads();

        const uint32_t Ks = smb + ((jt & 1) ? AS_K1 : AS_K0);
        const uint32_t Vs = smb + ((jt & 1) ? AS_V1 : AS_V0);

        // ---- S = Q @ K^T ----
        float s[8][4] = {};
        #pragma unroll
        for (int ks = 0; ks < 4; ks++) {
            #pragma unroll
            for (int jp = 0; jp < 4; jp++) {
                uint32_t bf[4];
                ldm4(bf, Ks + (jp * 16 + b_row) * AROWB + ks * 32 + b_off);
                mma_f16(s[2 * jp],     qa[ks][0], qa[ks][1], qa[ks][2], qa[ks][3], bf[0], bf[1]);
                mma_f16(s[2 * jp + 1], qa[ks][0], qa[ks][1], qa[ks][2], qa[ks][3], bf[2], bf[3]);
            }
        }

        // ---- mask (partially-banded tiles only) ----
        if ((kst + 63) > (qs + SRC)) {
            const int rlo = qs + w * 16 + lr;
            #pragma unroll
            for (int j = 0; j < 8; j++) {
                const int c0 = kst + j * 8 + 2 * lc;
                if (c0     > rlo + SRC)     s[j][0] = -1e30f;
                if (c0 + 1 > rlo + SRC)     s[j][1] = -1e30f;
                if (c0     > rlo + 8 + SRC) s[j][2] = -1e30f;
                if (c0 + 1 > rlo + 8 + SRC) s[j][3] = -1e30f;
            }
        }

        // ---- online softmax (rows r and r+8; quad shuffles) ----
        float mx_lo = -1e30f, mx_hi = -1e30f;
        #pragma unroll
        for (int j = 0; j < 8; j++) {
            mx_lo = fmaxf(mx_lo, fmaxf(s[j][0], s[j][1]));
            mx_hi = fmaxf(mx_hi, fmaxf(s[j][2], s[j][3]));
        }
        #pragma unroll
        for (int off = 1; off <= 2; off <<= 1) {
            mx_lo = fmaxf(mx_lo, __shfl_xor_sync(0xffffffffu, mx_lo, off));
            mx_hi = fmaxf(mx_hi, __shfl_xor_sync(0xffffffffu, mx_hi, off));
        }
        const float mn_lo = fmaxf(m_lo, mx_lo);
        const float mn_hi = fmaxf(m_hi, mx_hi);
        const float al_lo = __expf(m_lo - mn_lo);
        const float al_hi = __expf(m_hi - mn_hi);
        m_lo = mn_lo; m_hi = mn_hi;

        float sum_lo = 0.0f, sum_hi = 0.0f;
        const int prow = w * 16 + lr;
        #pragma unroll
        for (int j = 0; j < 8; j++) {
            float p0 = __expf(s[j][0] - mn_lo);
            float p1 = __expf(s[j][1] - mn_lo);
            float p2 = __expf(s[j][2] - mn_hi);
            float p3 = __expf(s[j][3] - mn_hi);
            sum_lo += p0 + p1;
            sum_hi += p2 + p3;
            *(uint32_t*)&Psh[prow * 72 + j * 8 + 2 * lc]       = ph2(p0, p1);
            *(uint32_t*)&Psh[(prow + 8) * 72 + j * 8 + 2 * lc] = ph2(p2, p3);
            o[j][0] *= al_lo; o[j][1] *= al_lo;
            o[j][2] *= al_hi; o[j][3] *= al_hi;
        }
        #pragma unroll
        for (int off = 1; off <= 2; off <<= 1) {
            sum_lo += __shfl_xor_sync(0xffffffffu, sum_lo, off);
            sum_hi += __shfl_xor_sync(0xffffffffu, sum_hi, off);
        }
        l_lo = l_lo * al_lo + sum_lo;
        l_hi = l_hi * al_hi + sum_hi;
        __syncwarp();   // Ps rows are warp-private; make stores visible in-warp

        // ---- O += P @ V (V fragments via ldmatrix.trans) ----
        #pragma unroll
        for (int ks = 0; ks < 4; ks++) {
            uint32_t pa[4];
            ldm4(pa, smb + AS_QS + (w * 16 + a_row) * AROWB + ks * 32 + a_off);
            #pragma unroll
            for (int jp = 0; jp < 4; jp++) {
                uint32_t vf[4];
                ldm4t(vf, Vs + (ks * 16 + a_row) * AROWB + (jp * 2 + (lane >> 4)) * 16);
                mma_f16(o[2 * jp],     pa[0], pa[1], pa[2], pa[3], vf[0], vf[1]);
                mma_f16(o[2 * jp + 1], pa[0], pa[1], pa[2], pa[3], vf[2], vf[3]);
            }
        }
    }

    // ---- finalize: scale by 1/l, write out ----
    const float li_lo = 1.0f / l_lo;
    const float li_hi = 1.0f / l_hi;
    const int t_lo = qs + w * 16 + lr;
    #pragma unroll
    for (int j = 0; j < 8; j++) {
        const int d = j * 8 + 2 * lc;
        float2 v0 = make_float2(o[j][0] * li_lo, o[j][1] * li_lo);
        float2 v1 = make_float2(o[j][2] * li_hi, o[j][3] * li_hi);
        *(float2*)&out[((size_t)(b * TT + t_lo)) * EE + h * DD + d] = v0;
        *(float2*)&out[((size_t)(b * TT + t_lo + 8)) * EE + h * DD + d] = v1;
    }
}

// ---------------------------------------------------------------------------
extern "C" void kernel_launch(void* const* d_in, const int* in_sizes, int n_in,
                              void* d_out, int out_size)
{
    (void)in_sizes; (void)n_in; (void)out_size;
    const float* x  = (const float*)d_in[0];
    const float* Wq = (const float*)d_in[1];
    const float* bq = (const float*)d_in[2];
    const float* Wk = (const float*)d_in[3];
    const float* bk = (const float*)d_in[4];
    const float* Wv = (const float*)d_in[5];
    const float* bv = (const float*)d_in[6];
    float* out = (float*)d_out;

    cudaFuncSetAttribute(qkv_gemm_tc,
                         cudaFuncAttributeMaxDynamicSharedMemorySize,
                         GEMM_SMEM_BYTES);
    cudaFuncSetAttribute(attn_kernel,
                         cudaFuncAttributeMaxDynamicSharedMemorySize,
                         ATTN_SMEM_BYTES);

    const int total4 = NX4 + 3 * NW4;               // 1,835,008
    convert_kernel<<<total4 / 256, 256>>>(x, Wq, Wk, Wv);

    dim3 ggrid(EE / 128, (BB * TT) / 128, 3);       // (8, 32, 3)
    qkv_gemm_tc<<<ggrid, 256, GEMM_SMEM_BYTES>>>(bq, bk, bv);

    dim3 agrid(TT / QROWS, NH, BB);                 // (8, 16, 2)
    attn_kernel<<<agrid, 512, ATTN_SMEM_BYTES>>>(out);
}

// round 12
// speedup vs baseline: 4.0364x; 1.0193x over previous
#include <cuda_runtime.h>
#include <cuda_fp16.h>
#include <math.h>
#include <cstdint>

#define BB 2
#define NH 16
#define TT 2048
#define DD 64
#define EE 1024
#define SRC 128

// Scratch (no cudaMalloc allowed). All fp16 (Q pre-scaled by log2e/8).
__device__ __half g_qh[BB * NH * TT * DD];
__device__ __half g_kh[BB * NH * TT * DD];
__device__ __half g_vh[BB * NH * TT * DD];
__device__ __half g_xh[BB * TT * EE];
__device__ __half g_wh[3][EE * EE];

__device__ __forceinline__ uint32_t ph2(float lo, float hi) {
    __half2 h = __floats2half2_rn(lo, hi);
    return *(uint32_t*)&h;
}

// D += A(16x16) * B(16x8), fp16 inputs, fp32 accum.
__device__ __forceinline__ void mma_f16(
    float* d, uint32_t a0, uint32_t a1, uint32_t a2, uint32_t a3,
    uint32_t b0, uint32_t b1)
{
    asm volatile(
        "mma.sync.aligned.m16n8k16.row.col.f32.f16.f16.f32 "
        "{%0,%1,%2,%3}, {%4,%5,%6,%7}, {%8,%9}, {%0,%1,%2,%3};"
        : "+f"(d[0]), "+f"(d[1]), "+f"(d[2]), "+f"(d[3])
        : "r"(a0), "r"(a1), "r"(a2), "r"(a3), "r"(b0), "r"(b1));
}

__device__ __forceinline__ void ldm4(uint32_t* r, uint32_t a) {
    asm volatile("ldmatrix.sync.aligned.m8n8.x4.shared.b16 {%0,%1,%2,%3}, [%4];"
        : "=r"(r[0]), "=r"(r[1]), "=r"(r[2]), "=r"(r[3]) : "r"(a));
}
__device__ __forceinline__ void ldm4t(uint32_t* r, uint32_t a) {
    asm volatile("ldmatrix.sync.aligned.m8n8.x4.trans.shared.b16 {%0,%1,%2,%3}, [%4];"
        : "=r"(r[0]), "=r"(r[1]), "=r"(r[2]), "=r"(r[3]) : "r"(a));
}

__device__ __forceinline__ void cp_async16(uint32_t smem_addr, const void* gptr) {
    asm volatile("cp.async.cg.shared.global [%0], [%1], 16;"
                 :: "r"(smem_addr), "l"(gptr));
}
#define CP_COMMIT() asm volatile("cp.async.commit_group;" ::: "memory")
#define CP_WAIT(N)  asm volatile("cp.async.wait_group %0;" :: "n"(N) : "memory")

// ===========================================================================
// Convert kernel: plain fp32 -> fp16 of x and Wq/Wk/Wv.
// ===========================================================================
#define NX4 ((BB * TT * EE) / 4)   // 1048576
#define NW4 ((EE * EE) / 4)        // 262144

__global__ __launch_bounds__(256) void convert_kernel(
    const float* __restrict__ x,
    const float* __restrict__ Wq,
    const float* __restrict__ Wk,
    const float* __restrict__ Wv)
{
    const int idx = blockIdx.x * blockDim.x + threadIdx.x;
    const float* __restrict__ src;
    __half* __restrict__ dst;
    int li;
    if (idx < NX4) {
        src = x; dst = g_xh; li = idx;
    } else {
        const int t = idx - NX4;
        const int z = t / NW4;
        li = t - z * NW4;
        src = (z == 0) ? Wq : (z == 1) ? Wk : Wv;
        dst = g_wh[z];
    }
    const float4 v = ((const float4*)src)[li];
    uint2 o;
    o.x = ph2(v.x, v.y);
    o.y = ph2(v.z, v.w);
    ((uint2*)dst)[li] = o;
}

// ===========================================================================
// QKV projection: y = x @ W^T + b -> fp16 [B,H,T,D].  fp16 m16n8k16 mma.
// Block tile 128x128, 256 threads (8 warps as 4Mx2N; warp tile 32x64).
// 64-K chunks, double-buffered cp.async; fragments via ldmatrix.x4.
// Q output pre-scaled by log2e/8 (softmax runs in exp2 domain).
// ===========================================================================
#define GROWB 144                  // bytes per smem row (64 halfs + pad)
#define G_A0 0u
#define G_A1 18432u
#define G_B0 36864u
#define G_B1 55296u
#define GEMM_SMEM_BYTES 73728

__global__ __launch_bounds__(256, 2) void qkv_gemm_tc(
    const float* __restrict__ bq,
    const float* __restrict__ bk,
    const float* __restrict__ bv)
{
    extern __shared__ char smc[];

    const int z = blockIdx.z;
    const __half* __restrict__ Wt  = g_wh[z];
    const float* __restrict__ bias = (z == 0) ? bq : (z == 1) ? bk : bv;
    __half* __restrict__ dst       = (z == 0) ? g_qh : (z == 1) ? g_kh : g_vh;
    const float osc = (z == 0) ? 0.125f * 1.44269504f : 1.0f;

    const int m0 = blockIdx.y * 128;
    const int n0 = blockIdx.x * 128;
    const int tid = threadIdx.x;
    const int lane = tid & 31;
    const int wid = tid >> 5;
    const int wm = wid & 3;        // 0..3 : M warp (32 rows)
    const int wn = wid >> 2;       // 0..1 : N warp (64 cols)
    const int lr = lane >> 2;      // 0..7
    const int lc = lane & 3;       // 0..3

    const uint32_t smb = (uint32_t)__cvta_generic_to_shared(smc);

    const int a_row = lane & 15;
    const int a_off = (lane >> 4) * 16;
    const int b_row = ((lane >> 4) * 8) + (lane & 7);
    const int b_off = ((lane >> 3) & 1) * 16;

    #pragma unroll
    for (int i = 0; i < 4; i++) {
        const int id = tid + i * 256;
        const int row = id >> 3;
        const int ch = id & 7;
        cp_async16(smb + G_A0 + row * GROWB + ch * 16,
                   &g_xh[(size_t)(m0 + row) * EE + ch * 8]);
        cp_async16(smb + G_B0 + row * GROWB + ch * 16,
                   &Wt[(size_t)(n0 + row) * EE + ch * 8]);
    }
    CP_COMMIT();

    float acc[2][8][4] = {};

    #pragma unroll 1
    for (int c = 0; c < EE / 64; c++) {
        CP_WAIT(0);
        __syncthreads();

        if (c + 1 < EE / 64) {
            const int k0 = (c + 1) * 64;
            const uint32_t aoff = ((c + 1) & 1) ? G_A1 : G_A0;
            const uint32_t boff = ((c + 1) & 1) ? G_B1 : G_B0;
            #pragma unroll
            for (int i = 0; i < 4; i++) {
                const int id = tid + i * 256;
                const int row = id >> 3;
                const int ch = id & 7;
                cp_async16(smb + aoff + row * GROWB + ch * 16,
                           &g_xh[(size_t)(m0 + row) * EE + k0 + ch * 8]);
                cp_async16(smb + boff + row * GROWB + ch * 16,
                           &Wt[(size_t)(n0 + row) * EE + k0 + ch * 8]);
            }
            CP_COMMIT();
        }

        const uint32_t A = smb + ((c & 1) ? G_A1 : G_A0);
        const uint32_t B = smb + ((c & 1) ? G_B1 : G_B0);

        uint32_t av[2][4][4];
        #pragma unroll
        for (int mt = 0; mt < 2; mt++)
            #pragma unroll
            for (int ks = 0; ks < 4; ks++)
                ldm4(av[mt][ks],
                     A + (wm * 32 + mt * 16 + a_row) * GROWB + ks * 32 + a_off);

        #pragma unroll
        for (int ks = 0; ks < 4; ks++) {
            #pragma unroll
            for (int jp = 0; jp < 4; jp++) {
                uint32_t bf[4];
                ldm4(bf, B + (wn * 64 + jp * 16 + b_row) * GROWB + ks * 32 + b_off);
                mma_f16(acc[0][2 * jp],     av[0][ks][0], av[0][ks][1], av[0][ks][2], av[0][ks][3], bf[0], bf[1]);
                mma_f16(acc[0][2 * jp + 1], av[0][ks][0], av[0][ks][1], av[0][ks][2], av[0][ks][3], bf[2], bf[3]);
                mma_f16(acc[1][2 * jp],     av[1][ks][0], av[1][ks][1], av[1][ks][2], av[1][ks][3], bf[0], bf[1]);
                mma_f16(acc[1][2 * jp + 1], av[1][ks][0], av[1][ks][1], av[1][ks][2], av[1][ks][3], bf[2], bf[3]);
            }
        }
    }

    #pragma unroll
    for (int mt = 0; mt < 2; mt++) {
        #pragma unroll
        for (int j = 0; j < 8; j++) {
            const int N = n0 + wn * 64 + j * 8 + 2 * lc;
            const int h = N >> 6, d = N & 63;
            const float b0 = __ldg(&bias[N]), b1 = __ldg(&bias[N + 1]);
            #pragma unroll
            for (int half_ = 0; half_ < 2; half_++) {
                const int M = m0 + wm * 32 + mt * 16 + lr + half_ * 8;
                const int bb = M >> 11, t = M & (TT - 1);
                const uint32_t hv = ph2((acc[mt][j][half_ * 2 + 0] + b0) * osc,
                                        (acc[mt][j][half_ * 2 + 1] + b1) * osc);
                *(uint32_t*)&dst[(((size_t)(bb * NH + h) * TT) + t) * DD + d] = hv;
            }
        }
    }
}

// ===========================================================================
// Flash attention, prefix-causal band (key j valid iff j <= i + SRC).
// One block = (b, h, 256-query tile). 512 threads (16 warps); warp = 16 rows.
// fp16 m16n8k16; fragments via ldmatrix (trans for V). K/V double-buffered
// cp.async with ONE barrier per tile. Softmax in exp2 domain (Q pre-scaled
// by log2e/8). Ps (fp16) overlays Q staging.
// ===========================================================================
#define QROWS 256
#define AROWB 144                     // bytes per smem row (64 halfs + pad)
#define AS_QS 0u                      // 256 rows -> 36864 B (reused as Ps)
#define AS_K0 36864u
#define AS_K1 46080u
#define AS_V0 55296u
#define AS_V1 64512u
#define ATTN_SMEM_BYTES 73728

__global__ __launch_bounds__(512, 1) void attn_kernel(float* __restrict__ out)
{
    extern __shared__ char smc[];
    __half* Psh = (__half*)smc;      // rows of 72 halfs (144B pitch)

    const int qtile = gridDim.x - 1 - blockIdx.x;  // heavy tiles first
    const int h = blockIdx.y;
    const int b = blockIdx.z;
    const int qs = qtile * QROWS;

    const __half* __restrict__ Qb = g_qh + (size_t)(b * NH + h) * TT * DD;
    const __half* __restrict__ Kb = g_kh + (size_t)(b * NH + h) * TT * DD;
    const __half* __restrict__ Vb = g_vh + (size_t)(b * NH + h) * TT * DD;

    const int tid = threadIdx.x;
    const int lane = tid & 31;
    const int w = tid >> 5;        // warp id 0..15: rows 16w..16w+15
    const int lr = lane >> 2;      // 0..7
    const int lc = lane & 3;       // 0..3

    const uint32_t smb = (uint32_t)__cvta_generic_to_shared(smc);

    const int a_row = lane & 15;
    const int a_off = (lane >> 4) * 16;
    const int b_row = ((lane >> 4) * 8) + (lane & 7);
    const int b_off = ((lane >> 3) & 1) * 16;

    // Q copy: 256 rows x 8 chunks = 2048; 4 per thread
    #pragma unroll
    for (int i = 0; i < 4; i++) {
        const int id = tid + i * 512;
        const int row = id >> 3;
        const int ch = id & 7;
        cp_async16(smb + AS_QS + row * AROWB + ch * 16,
                   &Qb[(size_t)(qs + row) * DD + ch * 8]);
    }
    CP_COMMIT();
    // K/V tile 0: 64 rows x 8 chunks = 512; 1 per thread each
    {
        const int row = tid >> 3;
        const int ch = tid & 7;
        cp_async16(smb + AS_K0 + row * AROWB + ch * 16, &Kb[(size_t)row * DD + ch * 8]);
        cp_async16(smb + AS_V0 + row * AROWB + ch * 16, &Vb[(size_t)row * DD + ch * 8]);
    }
    CP_COMMIT();

    CP_WAIT(1);          // Q landed (tile0 may still be in flight)
    __syncthreads();

    // hoist Q fragments: 4 ksteps x 4 regs
    uint32_t qa[4][4];
    #pragma unroll
    for (int ks = 0; ks < 4; ks++)
        ldm4(qa[ks], smb + AS_QS + (w * 16 + a_row) * AROWB + ks * 32 + a_off);

    float o[8][4] = {};
    float m_lo = -1e30f, m_hi = -1e30f, l_lo = 0.0f, l_hi = 0.0f;

    const int ntiles = min(TT / 64, qtile * 4 + 6);

    #pragma unroll 1
    for (int jt = 0; jt < ntiles; jt++) {
        const int kst = jt * 64;

        CP_WAIT(0);        // tile jt landed (only outstanding group)
        __syncthreads();   // + all warps done computing jt-1 (and qa hoists)

        if (jt + 1 < ntiles) {
            const int nk = (jt + 1) * 64;
            const uint32_t koff = ((jt + 1) & 1) ? AS_K1 : AS_K0;
            const uint32_t voff = ((jt + 1) & 1) ? AS_V1 : AS_V0;
            const int row = tid >> 3;
            const int ch = tid & 7;
            cp_async16(smb + koff + row * AROWB + ch * 16,
                       &Kb[(size_t)(nk + row) * DD + ch * 8]);
            cp_async16(smb + voff + row * AROWB + ch * 16,
                       &Vb[(size_t)(nk + row) * DD + ch * 8]);
            CP_COMMIT();
        }

        const uint32_t Ks = smb + ((jt & 1) ? AS_K1 : AS_K0);
        const uint32_t Vs = smb + ((jt & 1) ? AS_V1 : AS_V0);

        // ---- S = Q @ K^T (logits already in log2e units) ----
        float s[8][4] = {};
        #pragma unroll
        for (int ks = 0; ks < 4; ks++) {
            #pragma unroll
            for (int jp = 0; jp < 4; jp++) {
                uint32_t bf[4];
                ldm4(bf, Ks + (jp * 16 + b_row) * AROWB + ks * 32 + b_off);
                mma_f16(s[2 * jp],     qa[ks][0], qa[ks][1], qa[ks][2], qa[ks][3], bf[0], bf[1]);
                mma_f16(s[2 * jp + 1], qa[ks][0], qa[ks][1], qa[ks][2], qa[ks][3], bf[2], bf[3]);
            }
        }

        // ---- mask (partially-banded tiles only) ----
        if ((kst + 63) > (qs + SRC)) {
            const int rlo = qs + w * 16 + lr;
            #pragma unroll
            for (int j = 0; j < 8; j++) {
                const int c0 = kst + j * 8 + 2 * lc;
                if (c0     > rlo + SRC)     s[j][0] = -1e30f;
                if (c0 + 1 > rlo + SRC)     s[j][1] = -1e30f;
                if (c0     > rlo + 8 + SRC) s[j][2] = -1e30f;
                if (c0 + 1 > rlo + 8 + SRC) s[j][3] = -1e30f;
            }
        }

        // ---- online softmax, exp2 domain (rows r and r+8; quad shuffles) ----
        float mx_lo = -1e30f, mx_hi = -1e30f;
        #pragma unroll
        for (int j = 0; j < 8; j++) {
            mx_lo = fmaxf(mx_lo, fmaxf(s[j][0], s[j][1]));
            mx_hi = fmaxf(mx_hi, fmaxf(s[j][2], s[j][3]));
        }
        #pragma unroll
        for (int off = 1; off <= 2; off <<= 1) {
            mx_lo = fmaxf(mx_lo, __shfl_xor_sync(0xffffffffu, mx_lo, off));
            mx_hi = fmaxf(mx_hi, __shfl_xor_sync(0xffffffffu, mx_hi, off));
        }
        const float mn_lo = fmaxf(m_lo, mx_lo);
        const float mn_hi = fmaxf(m_hi, mx_hi);
        const float al_lo = exp2f(m_lo - mn_lo);
        const float al_hi = exp2f(m_hi - mn_hi);
        m_lo = mn_lo; m_hi = mn_hi;

        float sum_lo = 0.0f, sum_hi = 0.0f;
        const int prow = w * 16 + lr;
        #pragma unroll
        for (int j = 0; j < 8; j++) {
            float p0 = exp2f(s[j][0] - mn_lo);
            float p1 = exp2f(s[j][1] - mn_lo);
            float p2 = exp2f(s[j][2] - mn_hi);
            float p3 = exp2f(s[j][3] - mn_hi);
            sum_lo += p0 + p1;
            sum_hi += p2 + p3;
            *(uint32_t*)&Psh[prow * 72 + j * 8 + 2 * lc]       = ph2(p0, p1);
            *(uint32_t*)&Psh[(prow + 8) * 72 + j * 8 + 2 * lc] = ph2(p2, p3);
            o[j][0] *= al_lo; o[j][1] *= al_lo;
            o[j][2] *= al_hi; o[j][3] *= al_hi;
        }
        #pragma unroll
        for (int off = 1; off <= 2; off <<= 1) {
            sum_lo += __shfl_xor_sync(0xffffffffu, sum_lo, off);
            sum_hi += __shfl_xor_sync(0xffffffffu, sum_hi, off);
        }
        l_lo = l_lo * al_lo + sum_lo;
        l_hi = l_hi * al_hi + sum_hi;
        __syncwarp();   // Ps rows are warp-private; make stores visible in-warp

        // ---- O += P @ V (V fragments via ldmatrix.trans) ----
        #pragma unroll
        for (int ks = 0; ks < 4; ks++) {
            uint32_t pa[4];
            ldm4(pa, smb + AS_QS + (w * 16 + a_row) * AROWB + ks * 32 + a_off);
            #pragma unroll
            for (int jp = 0; jp < 4; jp++) {
                uint32_t vf[4];
                ldm4t(vf, Vs + (ks * 16 + a_row) * AROWB + (jp * 2 + (lane >> 4)) * 16);
                mma_f16(o[2 * jp],     pa[0], pa[1], pa[2], pa[3], vf[0], vf[1]);
                mma_f16(o[2 * jp + 1], pa[0], pa[1], pa[2], pa[3], vf[2], vf[3]);
            }
        }
    }

    // ---- finalize: scale by 1/l, write out ----
    const float li_lo = 1.0f / l_lo;
    const float li_hi = 1.0f / l_hi;
    const int t_lo = qs + w * 16 + lr;
    #pragma unroll
    for (int j = 0; j < 8; j++) {
        const int d = j * 8 + 2 * lc;
        float2 v0 = make_float2(o[j][0] * li_lo, o[j][1] * li_lo);
        float2 v1 = make_float2(o[j][2] * li_hi, o[j][3] * li_hi);
        *(float2*)&out[((size_t)(b * TT + t_lo)) * EE + h * DD + d] = v0;
        *(float2*)&out[((size_t)(b * TT + t_lo + 8)) * EE + h * DD + d] = v1;
    }
}

// ---------------------------------------------------------------------------
extern "C" void kernel_launch(void* const* d_in, const int* in_sizes, int n_in,
                              void* d_out, int out_size)
{
    (void)in_sizes; (void)n_in; (void)out_size;
    const float* x  = (const float*)d_in[0];
    const float* Wq = (const float*)d_in[1];
    const float* bq = (const float*)d_in[2];
    const float* Wk = (const float*)d_in[3];
    const float* bk = (const float*)d_in[4];
    const float* Wv = (const float*)d_in[5];
    const float* bv = (const float*)d_in[6];
    float* out = (float*)d_out;

    cudaFuncSetAttribute(qkv_gemm_tc,
                         cudaFuncAttributeMaxDynamicSharedMemorySize,
                         GEMM_SMEM_BYTES);
    cudaFuncSetAttribute(attn_kernel,
                         cudaFuncAttributeMaxDynamicSharedMemorySize,
                         ATTN_SMEM_BYTES);

    const int total4 = NX4 + 3 * NW4;               // 1,835,008
    convert_kernel<<<total4 / 256, 256>>>(x, Wq, Wk, Wv);

    dim3 ggrid(EE / 128, (BB * TT) / 128, 3);       // (8, 32, 3)
    qkv_gemm_tc<<<ggrid, 256, GEMM_SMEM_BYTES>>>(bq, bk, bv);

    dim3 agrid(TT / QROWS, NH, BB);                 // (8, 16, 2)
    attn_kernel<<<agrid, 512, ATTN_SMEM_BYTES>>>(out);
}